// round 15
// baseline (speedup 1.0000x reference)
#include <cuda_runtime.h>
#include <math.h>
#include <stdint.h>

#define Bsz   4
#define Tn    1024
#define Dm    1024
#define Hn    16
#define Mrows (Bsz*Tn)
#define DFFn  4096
#define NSMALL 272
#define QKVN  4096   // qkv(3072) + memval(1024) merged

__device__ float g_h     [Mrows*Dm];
__device__ float g_qkv   [Mrows*QKVN];
__device__ float g_small [Mrows*NSMALL];
__device__ float g_seq   [Mrows*Dm];
__device__ float g_jw    [Bsz*Hn*Tn*8];
__device__ float g_rl    [Bsz*Hn*Tn*6];
__device__ float g_mscore[Bsz*Hn*Tn];
__device__ float g_x2    [Mrows*Dm];
__device__ float g_h2    [Mrows*Dm];
__device__ float g_ff1   [Mrows*DFFn];
__device__ float g_powd  [Hn*Tn];
__device__ float g_wcat  [NSMALL*Dm];
__device__ float g_bcat  [NSMALL];
__device__ float g_wqkv  [4*Dm*Dm];
__device__ float g_bqkvm [QKVN];
__device__ float g_wout  [Dm*Dm];
__device__ float g_wfc1  [DFFn*Dm];
__device__ float g_wfc2  [Dm*DFFn];

__device__ __forceinline__ float sigf(float x){ return 1.f/(1.f+__expf(-x)); }
__device__ __forceinline__ float geluf(float v){
    return 0.5f*v*(1.f + erff(v*0.7071067811865476f));
}
__device__ __forceinline__ uint32_t rna_u(uint32_t x){
    uint32_t r; asm("cvt.rna.tf32.f32 %0, %1;" : "=r"(r) : "r"(x)); return r;
}
__device__ __forceinline__ float rna_f(float x){
    return __uint_as_float(rna_u(__float_as_uint(x)));
}
__device__ __forceinline__ void mma_tf32(float* d, const uint32_t* a, const uint32_t* b){
    asm volatile("mma.sync.aligned.m16n8k8.row.col.f32.tf32.tf32.f32 "
        "{%0,%1,%2,%3}, {%4,%5,%6,%7}, {%8,%9}, {%0,%1,%2,%3};"
        : "+f"(d[0]), "+f"(d[1]), "+f"(d[2]), "+f"(d[3])
        : "r"(a[0]), "r"(a[1]), "r"(a[2]), "r"(a[3]), "r"(b[0]), "r"(b[1]));
}
__device__ __forceinline__ void cpa16(uint32_t dst, const void* src){
    asm volatile("cp.async.cg.shared.global [%0], [%1], 16;" :: "r"(dst), "l"(src) : "memory");
}
__device__ __forceinline__ void cpa_commit(){
    asm volatile("cp.async.commit_group;" ::: "memory");
}
template<int N>
__device__ __forceinline__ void cpa_wait(){
    asm volatile("cp.async.wait_group %0;" :: "n"(N) : "memory");
}
__device__ __forceinline__ int fwz(int r, int gi, int off){
    return r*64 + ((((gi ^ r) & 7) | (gi & 8)) << 2) + off;
}

// ---------------- merged weight tf32 pre-round + bias concat ----------------
#define N4_QKV  (3*Dm*Dm/4)
#define N4_DM   (Dm*Dm/4)
#define N4_FF   (DFFn*Dm/4)
#define N4_BIAS (QKVN/4)
#define N4_TOT  (N4_QKV + 2*N4_DM + 2*N4_FF + N4_BIAS)
__global__ __launch_bounds__(256) void roundw_all_kernel(
    const float4* __restrict__ qkv_w, const float4* __restrict__ memv_w,
    const float4* __restrict__ out_w, const float4* __restrict__ fc1_w,
    const float4* __restrict__ fc2_w, const float4* __restrict__ qkv_b,
    const float4* __restrict__ memv_b)
{
    const int i = blockIdx.x*256 + threadIdx.x;
    if (i >= N4_TOT) return;
    int k = i;
    const float4* src; float4* dst;
    if      (k < N4_QKV){ src=qkv_w; dst=(float4*)g_wqkv; }
    else if ((k -= N4_QKV) < N4_DM){ src=memv_w; dst=(float4*)g_wqkv + N4_QKV; }
    else if ((k -= N4_DM)  < N4_DM){ src=out_w;  dst=(float4*)g_wout; }
    else if ((k -= N4_DM)  < N4_FF){ src=fc1_w;  dst=(float4*)g_wfc1; }
    else if ((k -= N4_FF)  < N4_FF){ src=fc2_w;  dst=(float4*)g_wfc2; }
    else {
        k -= N4_FF;
        ((float4*)g_bqkvm)[k] = (k < 3*Dm/4) ? qkv_b[k] : memv_b[k - 3*Dm/4];
        return;
    }
    float4 v = src[k];
    v.x=rna_f(v.x); v.y=rna_f(v.y); v.z=rna_f(v.z); v.w=rna_f(v.w);
    dst[k] = v;
}

// ============================================================================
// tf32 GEMM — R11 proven: CTA 128x128, 256 thr / 8 warps, warp 32x64,
// K-chunk 32, cp.async 3-stage (96KB), 2 CTAs/SM.
// ============================================================================
enum { EPI_BIAS=0, EPI_BIAS_RES=1, EPI_BIAS_GELU=2 };

template<int EPI, int RND>
__global__ __launch_bounds__(256, 2) void tgemm_kernel(
    const float* __restrict__ A, const float* __restrict__ W,
    const float* __restrict__ bias, const float* __restrict__ res,
    float* __restrict__ C, int M, int N, int K)
{
    extern __shared__ uint32_t sm[];
    const uint32_t smb = (uint32_t)__cvta_generic_to_shared(sm);

    const int tid  = threadIdx.x;
    const int lane = tid & 31;
    const int warp = tid >> 5;
    const int g    = lane >> 2;
    const int tig  = lane & 3;
    const int wm   = (warp & 3) * 32;
    const int wn   = (warp >> 2) * 64;
    const int bm   = blockIdx.y * 128;
    const int bn   = blockIdx.x * 128;

    float acc[2][8][4];
    #pragma unroll
    for (int i=0;i<2;i++)
        #pragma unroll
        for (int j=0;j<8;j++)
            #pragma unroll
            for (int c=0;c<4;c++) acc[i][j][c]=0.f;

    const int r = tid >> 3;
    const int q = tid & 7;
    const int nchunks = K >> 5;

    int istage = 0;
    auto issue = [&](int i){
        const uint32_t aB = smb + (uint32_t)istage*32768u;
        const uint32_t bB = aB + 16384u;
        istage = (istage == 2) ? 0 : istage + 1;
        const int kofs = i << 5;
        #pragma unroll
        for (int it = 0; it < 4; it++){
            const int rr = r + it*32;
            const uint32_t off = ((uint32_t)rr*32u + (uint32_t)((q ^ (rr & 7)) << 2)) * 4u;
            cpa16(aB + off, &A[(size_t)(bm + rr)*K + kofs + q*4]);
            cpa16(bB + off, &W[(size_t)(bn + rr)*K + kofs + q*4]);
        }
        cpa_commit();
    };

    issue(0);
    if (nchunks > 1) issue(1);

    int cstage = 0;
    for (int i = 0; i < nchunks; i++){
        if (i + 2 < nchunks){ issue(i + 2); cpa_wait<2>(); }
        else if (i + 1 < nchunks) cpa_wait<1>();
        else cpa_wait<0>();
        __syncthreads();

        const uint32_t* As = sm + (size_t)cstage*8192;
        const uint32_t* Bs = As + 4096;
        cstage = (cstage == 2) ? 0 : cstage + 1;

        #pragma unroll
        for (int ks = 0; ks < 4; ks++){
            uint32_t af[2][4];
            #pragma unroll
            for (int ii = 0; ii < 2; ii++){
                const int m  = wm + ii*16 + g;
                const int g0 = ((2*ks)   ^ (m & 7)) << 2;
                const int g1 = ((2*ks+1) ^ (m & 7)) << 2;
                af[ii][0] = As[m*32     + g0 + tig];
                af[ii][1] = As[(m+8)*32 + g0 + tig];
                af[ii][2] = As[m*32     + g1 + tig];
                af[ii][3] = As[(m+8)*32 + g1 + tig];
            }
            uint32_t bf[8][2];
            #pragma unroll
            for (int j = 0; j < 8; j++){
                const int n  = wn + j*8 + g;
                const int g0 = ((2*ks)   ^ (n & 7)) << 2;
                const int g1 = ((2*ks+1) ^ (n & 7)) << 2;
                bf[j][0] = Bs[n*32 + g0 + tig];
                bf[j][1] = Bs[n*32 + g1 + tig];
            }
            #pragma unroll
            for (int ii = 0; ii < 2; ii++)
                #pragma unroll
                for (int j = 0; j < 8; j++)
                    mma_tf32(acc[ii][j], af[ii], bf[j]);
        }
        __syncthreads();
    }

    #pragma unroll
    for (int i = 0; i < 2; i++){
        const int row = bm + wm + i*16 + g;
        #pragma unroll
        for (int j = 0; j < 8; j++){
            const int col = bn + wn + j*8 + tig*2;
            const float b0 = bias[col], b1 = bias[col+1];
            float v0 = acc[i][j][0] + b0;
            float v1 = acc[i][j][1] + b1;
            float v2 = acc[i][j][2] + b0;
            float v3 = acc[i][j][3] + b1;
            if (EPI == EPI_BIAS_GELU){
                v0=geluf(v0); v1=geluf(v1); v2=geluf(v2); v3=geluf(v3);
            } else if (EPI == EPI_BIAS_RES){
                const float2 r0 = *reinterpret_cast<const float2*>(&res[(size_t)row*N + col]);
                const float2 r1 = *reinterpret_cast<const float2*>(&res[(size_t)(row+8)*N + col]);
                v0+=r0.x; v1+=r0.y; v2+=r1.x; v3+=r1.y;
            }
            if (RND){
                v0=rna_f(v0); v1=rna_f(v1); v2=rna_f(v2); v3=rna_f(v3);
            }
            *reinterpret_cast<float2*>(&C[(size_t)row*N + col])     = make_float2(v0,v1);
            *reinterpret_cast<float2*>(&C[(size_t)(row+8)*N + col]) = make_float2(v2,v3);
        }
    }
}
#define TG_SMEM (3*8192*4)

// ============================================================================
// tf32 flash attention, occupancy-first: Q-tile 64, 128 thr / 4 warps,
// SINGLE-stage KV (64KB smem total) -> 3 CTAs/SM = 12 warps/SM.
// Co-resident CTAs hide the exposed KV load + softmax latency.
// LPT: qt = 15 - blockIdx.x.
// smem words: Q @0 (4096), P @4096 (4096), K @8192 (4096), V @12288 (4096).
// ============================================================================
#define AQ_OFF 0
#define AP_OFF 4096
#define AK_OFF 8192
#define AV_OFF 12288
#define ATTN_SMEM (16384*4)

__global__ __launch_bounds__(128, 3) void attn_mma_kernel()
{
    extern __shared__ uint32_t smA[];
    const uint32_t smb = (uint32_t)__cvta_generic_to_shared(smA);
    const int tid  = threadIdx.x;
    const int lane = tid & 31;
    const int warp = tid >> 5;
    const int g    = lane >> 2;
    const int tig  = lane & 3;
    const int wm   = warp * 16;
    const int qt   = (Tn/64 - 1) - blockIdx.x;   // heavy tiles first
    const int bh   = blockIdx.y;
    const int b    = bh >> 4, h = bh & 15;
    const int nkt  = qt + 1;

    const int lr = tid >> 1;
    const int lg0 = (tid & 1) * 8;

    // Q tile (once)
    {
        const float* src = &g_qkv[((size_t)(b*Tn + qt*64 + lr))*QKVN + h*64];
        #pragma unroll
        for (int i = 0; i < 8; i++){
            const int gi = lg0 + i;
            const int gs = ((gi ^ (lr & 7)) & 7) | (gi & 8);
            cpa16(smb + (uint32_t)(AQ_OFF + lr*64 + gs*4)*4u, src + gi*4);
        }
        cpa_commit();
    }
    auto issueKV = [&](int kt){
        const float* srcK = &g_qkv[((size_t)(b*Tn + kt*64 + lr))*QKVN + 1024 + h*64];
        #pragma unroll
        for (int i = 0; i < 8; i++){
            const int gi = lg0 + i;
            const int gs = ((gi ^ (lr & 7)) & 7) | (gi & 8);
            const uint32_t woff = (uint32_t)(lr*64 + gs*4);
            cpa16(smb + (uint32_t)(AK_OFF + woff)*4u, srcK + gi*4);
            cpa16(smb + (uint32_t)(AV_OFF + woff)*4u, srcK + 1024 + gi*4);
        }
        cpa_commit();
    };
    issueKV(0);

    float M0=-1e30f, M1=-1e30f, L0=0.f, L1=0.f;
    float o[8][4];
    #pragma unroll
    for (int j=0;j<8;j++)
        #pragma unroll
        for (int c=0;c<4;c++) o[j][c]=0.f;

    const uint32_t* Qs = smA + AQ_OFF;
    uint32_t* Ps = smA + AP_OFF;
    const uint32_t* Ks = smA + AK_OFF;
    const uint32_t* Vs = smA + AV_OFF;

    for (int kt = 0; kt < nkt; kt++){
        cpa_wait<0>();
        __syncthreads();          // KV[kt] visible to all warps

        float s[8][4];
        #pragma unroll
        for (int j=0;j<8;j++)
            #pragma unroll
            for (int c=0;c<4;c++) s[j][c]=0.f;

        #pragma unroll
        for (int ks = 0; ks < 8; ks++){
            uint32_t a[4];
            const int m = wm + g;
            a[0] = Qs[fwz(m,   2*ks,   tig)];
            a[1] = Qs[fwz(m+8, 2*ks,   tig)];
            a[2] = Qs[fwz(m,   2*ks+1, tig)];
            a[3] = Qs[fwz(m+8, 2*ks+1, tig)];
            #pragma unroll
            for (int j = 0; j < 8; j++){
                uint32_t bfr[2];
                const int n = 8*j + g;
                bfr[0] = Ks[fwz(n, 2*ks,   tig)];
                bfr[1] = Ks[fwz(n, 2*ks+1, tig)];
                mma_tf32(s[j], a, bfr);
            }
        }

        const bool diag = (kt == qt);
        #pragma unroll
        for (int j = 0; j < 8; j++){
            float v0 = s[j][0]*0.125f, v1 = s[j][1]*0.125f;
            float v2 = s[j][2]*0.125f, v3 = s[j][3]*0.125f;
            if (diag){
                const int c0 = 8*j + 2*tig, c1 = c0 + 1;
                const int r0 = wm + g, r1 = r0 + 8;
                if (c0 > r0) v0 = -1e30f;
                if (c1 > r0) v1 = -1e30f;
                if (c0 > r1) v2 = -1e30f;
                if (c1 > r1) v3 = -1e30f;
            }
            s[j][0]=v0; s[j][1]=v1; s[j][2]=v2; s[j][3]=v3;
        }

        float tm0 = -1e30f, tm1 = -1e30f;
        #pragma unroll
        for (int j = 0; j < 8; j++){
            tm0 = fmaxf(tm0, fmaxf(s[j][0], s[j][1]));
            tm1 = fmaxf(tm1, fmaxf(s[j][2], s[j][3]));
        }
        tm0 = fmaxf(tm0, __shfl_xor_sync(0xffffffffu, tm0, 1));
        tm0 = fmaxf(tm0, __shfl_xor_sync(0xffffffffu, tm0, 2));
        tm1 = fmaxf(tm1, __shfl_xor_sync(0xffffffffu, tm1, 1));
        tm1 = fmaxf(tm1, __shfl_xor_sync(0xffffffffu, tm1, 2));
        const float Mn0 = fmaxf(M0, tm0), Mn1 = fmaxf(M1, tm1);
        const float f0 = __expf(M0 - Mn0), f1 = __expf(M1 - Mn1);
        float ps0 = 0.f, ps1 = 0.f;
        #pragma unroll
        for (int j = 0; j < 8; j++){
            const float p0 = __expf(s[j][0] - Mn0);
            const float p1 = __expf(s[j][1] - Mn0);
            const float p2 = __expf(s[j][2] - Mn1);
            const float p3 = __expf(s[j][3] - Mn1);
            ps0 += p0 + p1; ps1 += p2 + p3;
            const int c = 8*j + 2*tig;
            const int gi = c >> 2, off = c & 3;
            uint32_t* p01 = &Ps[fwz(wm+g,   gi, off)];
            uint32_t* p23 = &Ps[fwz(wm+g+8, gi, off)];
            p01[0] = rna_u(__float_as_uint(p0)); p01[1] = rna_u(__float_as_uint(p1));
            p23[0] = rna_u(__float_as_uint(p2)); p23[1] = rna_u(__float_as_uint(p3));
            o[j][0] *= f0; o[j][1] *= f0; o[j][2] *= f1; o[j][3] *= f1;
        }
        ps0 += __shfl_xor_sync(0xffffffffu, ps0, 1);
        ps0 += __shfl_xor_sync(0xffffffffu, ps0, 2);
        ps1 += __shfl_xor_sync(0xffffffffu, ps1, 1);
        ps1 += __shfl_xor_sync(0xffffffffu, ps1, 2);
        L0 = L0*f0 + ps0; L1 = L1*f1 + ps1;
        M0 = Mn0; M1 = Mn1;
        __syncwarp();

        #pragma unroll
        for (int kk = 0; kk < 8; kk++){
            uint32_t a[4];
            const int m = wm + g;
            a[0] = Ps[fwz(m,   2*kk,   tig)];
            a[1] = Ps[fwz(m+8, 2*kk,   tig)];
            a[2] = Ps[fwz(m,   2*kk+1, tig)];
            a[3] = Ps[fwz(m+8, 2*kk+1, tig)];
            #pragma unroll
            for (int j = 0; j < 8; j++){
                uint32_t bfr[2];
                const int n = 8*j + g;
                const int gi = n >> 2, off = n & 3;
                bfr[0] = Vs[fwz(8*kk + tig,     gi, off)];
                bfr[1] = Vs[fwz(8*kk + 4 + tig, gi, off)];
                mma_tf32(o[j], a, bfr);
            }
        }
        __syncthreads();          // all warps done reading K/V[kt]
        if (kt + 1 < nkt) issueKV(kt + 1);
    }

    const float i0 = 1.f / L0, i1 = 1.f / L1;
    const int r0 = b*Tn + qt*64 + wm + g;
    #pragma unroll
    for (int j = 0; j < 8; j++){
        const int col = h*64 + 8*j + 2*tig;
        *reinterpret_cast<float2*>(&g_seq[(size_t)r0*Dm + col]) =
            make_float2(o[j][0]*i0, o[j][1]*i0);
        *reinterpret_cast<float2*>(&g_seq[(size_t)(r0+8)*Dm + col]) =
            make_float2(o[j][2]*i1, o[j][3]*i1);
    }
}

// ---------------- LayerNorm (tf32-rounded out) ----------------
__global__ __launch_bounds__(256) void ln_kernel(const float* __restrict__ x,
    const float* __restrict__ g, const float* __restrict__ b, float* __restrict__ out)
{
    const int row = blockIdx.x;
    const int tid = threadIdx.x;
    const float4 v = reinterpret_cast<const float4*>(x + (size_t)row*Dm)[tid];
    float s  = v.x+v.y+v.z+v.w;
    float s2 = v.x*v.x+v.y*v.y+v.z*v.z+v.w*v.w;
    #pragma unroll
    for (int off=16; off>0; off>>=1){
        s  += __shfl_xor_sync(0xffffffffu, s,  off);
        s2 += __shfl_xor_sync(0xffffffffu, s2, off);
    }
    __shared__ float ss[8], ss2[8];
    if ((tid & 31)==0){ ss[tid>>5]=s; ss2[tid>>5]=s2; }
    __syncthreads();
    float ts=0.f, ts2=0.f;
    #pragma unroll
    for (int i=0;i<8;i++){ ts+=ss[i]; ts2+=ss2[i]; }
    const float mu  = ts*(1.f/1024.f);
    const float inv = rsqrtf(ts2*(1.f/1024.f) - mu*mu + 1e-5f);
    const float4 gv = reinterpret_cast<const float4*>(g)[tid];
    const float4 bv = reinterpret_cast<const float4*>(b)[tid];
    float4 o;
    o.x=rna_f((v.x-mu)*inv*gv.x+bv.x); o.y=rna_f((v.y-mu)*inv*gv.y+bv.y);
    o.z=rna_f((v.z-mu)*inv*gv.z+bv.z); o.w=rna_f((v.w-mu)*inv*gv.w+bv.w);
    reinterpret_cast<float4*>(out + (size_t)row*Dm)[tid] = o;
}

// ---------------- concat small weights ----------------
__global__ __launch_bounds__(256) void wcat_kernel(
    const float* __restrict__ w1w, const float* __restrict__ w2w,
    const float* __restrict__ w1r, const float* __restrict__ w2r,
    const float* __restrict__ memg_w, const float* __restrict__ memg_b)
{
    const int r = blockIdx.x;
    const float* src;
    if      (r < 64)  src = w1w + (size_t)r*Dm;
    else if (r < 128) src = w2w + (size_t)(r-64)*Dm;
    else if (r < 192) src = w1r + (size_t)(r-128)*Dm;
    else if (r < 256) src = w2r + (size_t)(r-192)*Dm;
    else              src = memg_w + (size_t)(r-256)*Dm;
    reinterpret_cast<float4*>(g_wcat + (size_t)r*Dm)[threadIdx.x] =
        reinterpret_cast<const float4*>(src)[threadIdx.x];
    if (r == 0){
        for (int c = threadIdx.x; c < NSMALL; c += 256)
            g_bcat[c] = (c < 256) ? 0.f : memg_b[c-256];
    }
}

// ---------------- fp32 SGEMM for the 272-col small projection ----------------
__global__ __launch_bounds__(256) void sgemm_small_kernel(
    const float* __restrict__ A, const float* __restrict__ W,
    const float* __restrict__ bias, float* __restrict__ C, int M, int N, int K)
{
    __shared__ float As[16][128];
    __shared__ float Ws[16][128];
    const int tid = threadIdx.x;
    const int bm  = blockIdx.y * 128;
    const int bn  = blockIdx.x * 128;
    const int ty  = tid >> 4;
    const int tx  = tid & 15;
    const int lr  = tid >> 2;
    const int lk  = (tid & 3) << 2;

    float acc[8][8];
    #pragma unroll
    for (int i=0;i<8;i++)
        #pragma unroll
        for (int j=0;j<8;j++) acc[i][j]=0.f;

    for (int k0 = 0; k0 < K; k0 += 16){
        #pragma unroll
        for (int it=0; it<2; it++){
            const int r = lr + it*64;
            const float4 a = *reinterpret_cast<const float4*>(&A[(size_t)(bm + r)*K + k0 + lk]);
            As[lk+0][r]=a.x; As[lk+1][r]=a.y; As[lk+2][r]=a.z; As[lk+3][r]=a.w;
        }
        #pragma unroll
        for (int it=0; it<2; it++){
            const int r = lr + it*64;
            const int n = bn + r;
            float4 w = make_float4(0.f,0.f,0.f,0.f);
            if (n < N) w = *reinterpret_cast<const float4*>(&W[(size_t)n*K + k0 + lk]);
            Ws[lk+0][r]=w.x; Ws[lk+1][r]=w.y; Ws[lk+2][r]=w.z; Ws[lk+3][r]=w.w;
        }
        __syncthreads();
        #pragma unroll
        for (int kk=0; kk<16; kk++){
            float ar[8], wr[8];
            *reinterpret_cast<float4*>(&ar[0]) = *reinterpret_cast<const float4*>(&As[kk][ty*4]);
            *reinterpret_cast<float4*>(&ar[4]) = *reinterpret_cast<const float4*>(&As[kk][ty*4+64]);
            *reinterpret_cast<float4*>(&wr[0]) = *reinterpret_cast<const float4*>(&Ws[kk][tx*4]);
            *reinterpret_cast<float4*>(&wr[4]) = *reinterpret_cast<const float4*>(&Ws[kk][tx*4+64]);
            #pragma unroll
            for (int i=0;i<8;i++)
                #pragma unroll
                for (int j=0;j<8;j++)
                    acc[i][j] = fmaf(ar[i], wr[j], acc[i][j]);
        }
        __syncthreads();
    }

    #pragma unroll
    for (int i=0;i<8;i++){
        const int m = bm + ty*4 + ((i<4) ? i : 64 + (i-4));
        #pragma unroll
        for (int jb=0; jb<2; jb++){
            const int n = bn + tx*4 + jb*64;
            if (n < N){
                float v0=acc[i][jb*4+0]+bias[n],   v1=acc[i][jb*4+1]+bias[n+1];
                float v2=acc[i][jb*4+2]+bias[n+2], v3=acc[i][jb*4+3]+bias[n+3];
                *reinterpret_cast<float4*>(&C[(size_t)m*N + n]) = make_float4(v0,v1,v2,v3);
            }
        }
    }
}

// ---------------- Plucker lines + J permutation ----------------
__global__ __launch_bounds__(256) void lines_kernel()
{
    const int idx = blockIdx.x*256 + threadIdx.x;
    const int row = idx >> 4;
    const int h   = idx & 15;
    const int b   = row >> 10;
    const int t   = row & 1023;
    const float* s = g_small + (size_t)row*NSMALL;

    float p1[4], p2[4], L[6];
    if (t == 0){ p1[0]=p1[1]=p1[2]=p1[3]=0.f; }
    else {
        const float* sp = s - NSMALL;
        #pragma unroll
        for (int p=0;p<4;p++) p1[p] = sp[h*4+p];
    }
    #pragma unroll
    for (int p=0;p<4;p++) p2[p] = s[64 + h*4 + p];

    L[0]=p1[0]*p2[1]-p1[1]*p2[0];
    L[1]=p1[0]*p2[2]-p1[2]*p2[0];
    L[2]=p1[0]*p2[3]-p1[3]*p2[0];
    L[3]=p1[1]*p2[2]-p1[2]*p2[1];
    L[4]=p1[1]*p2[3]-p1[3]*p2[1];
    L[5]=p1[2]*p2[3]-p1[3]*p2[2];
    float nn = sqrtf(L[0]*L[0]+L[1]*L[1]+L[2]*L[2]+L[3]*L[3]+L[4]*L[4]+L[5]*L[5]);
    float inv = 1.f / fmaxf(nn, 1e-12f);
    float* jw = &g_jw[(((size_t)(b*Hn+h))*Tn + t)*8];
    jw[0]= L[5]*inv; jw[1]=-L[4]*inv; jw[2]= L[3]*inv;
    jw[3]= L[2]*inv; jw[4]=-L[1]*inv; jw[5]= L[0]*inv;
    jw[6]=0.f; jw[7]=0.f;

    #pragma unroll
    for (int p=0;p<4;p++){ p1[p]=s[128+h*4+p]; p2[p]=s[192+h*4+p]; }
    L[0]=p1[0]*p2[1]-p1[1]*p2[0];
    L[1]=p1[0]*p2[2]-p1[2]*p2[0];
    L[2]=p1[0]*p2[3]-p1[3]*p2[0];
    L[3]=p1[1]*p2[2]-p1[2]*p2[1];
    L[4]=p1[1]*p2[3]-p1[3]*p2[1];
    L[5]=p1[2]*p2[3]-p1[3]*p2[2];
    nn = sqrtf(L[0]*L[0]+L[1]*L[1]+L[2]*L[2]+L[3]*L[3]+L[4]*L[4]+L[5]*L[5]);
    inv = 1.f / fmaxf(nn, 1e-12f);
    float* rl = &g_rl[(((size_t)(b*Hn+h))*Tn + t)*6];
    #pragma unroll
    for (int p=0;p<6;p++) rl[p] = L[p]*inv;
}

// ---------------- decay^delta table ----------------
__global__ void pow_kernel(const float* __restrict__ decay_logits)
{
    const int h = blockIdx.x;
    const float d  = 1.f/(1.f+expf(-decay_logits[h]));
    const float l2 = log2f(d);
    for (int t = threadIdx.x; t < Tn; t += blockDim.x)
        g_powd[h*Tn + t] = exp2f((float)t * l2);
}

// ---------------- mem_score: grid (bh, 4 q-chunks of 256) ----------------
__global__ __launch_bounds__(256) void mscore_kernel()
{
    const int bh = blockIdx.x;
    const int qc = blockIdx.y;
    const int h  = bh & 15;
    const int jmax = (qc + 1) * 256;
    __shared__ float jw_s[Tn*8];
    __shared__ float pw_s[Tn];
    const int tid = threadIdx.x;
    for (int i = tid; i < jmax*2; i += 256)
        reinterpret_cast<float4*>(jw_s)[i] =
            reinterpret_cast<const float4*>(g_jw + (size_t)bh*Tn*8)[i];
    for (int i = tid; i < Tn; i += 256) pw_s[i] = g_powd[h*Tn + i];
    __syncthreads();

    const int q = qc*256 + tid;
    float r0,r1,r2,r3,r4,r5;
    const float* rp = &g_rl[((size_t)bh*Tn + q)*6];
    r0=rp[0]; r1=rp[1]; r2=rp[2]; r3=rp[3]; r4=rp[4]; r5=rp[5];
    float acc = 0.f;
    for (int j = 0; j < q; j++){
        const float2 w0 = *reinterpret_cast<const float2*>(&jw_s[j*8+0]);
        const float2 w1 = *reinterpret_cast<const float2*>(&jw_s[j*8+2]);
        const float2 w2 = *reinterpret_cast<const float2*>(&jw_s[j*8+4]);
        float dot = r0*w0.x;
        dot = fmaf(r1, w0.y, dot);
        dot = fmaf(r2, w1.x, dot);
        dot = fmaf(r3, w1.y, dot);
        dot = fmaf(r4, w2.x, dot);
        dot = fmaf(r5, w2.y, dot);
        acc = fmaf(fabsf(dot), pw_s[q-j], acc);
    }
    g_mscore[(size_t)bh*Tn + q] = acc;
}

// ---------------- gated+fuse merged ----------------
__global__ __launch_bounds__(256) void gatedfuse_kernel(const float* __restrict__ mem_scale)
{
    const int row = blockIdx.x;
    const int b = row >> 10, t = row & 1023;
    const int tid = threadIdx.x;
    __shared__ float gv_s;
    if (tid < 16){
        const float ms = g_mscore[(size_t)(b*Hn+tid)*Tn + t];
        const float gt = sigf(g_small[(size_t)row*NSMALL + 256 + tid]);
        float v = sigf(ms * mem_scale[tid]) * gt;
        v += __shfl_xor_sync(0xffffu, v, 1, 16);
        v += __shfl_xor_sync(0xffffu, v, 2, 16);
        v += __shfl_xor_sync(0xffffu, v, 4, 16);
        v += __shfl_xor_sync(0xffffu, v, 8, 16);
        if (tid == 0) gv_s = v * (1.f/16.f);
    }
    __syncthreads();
    const float gv = gv_s;
    float4* sp = reinterpret_cast<float4*>(&g_seq[(size_t)row*Dm]);
    const float4* mp = reinterpret_cast<const float4*>(&g_qkv[(size_t)row*QKVN + 3072]);
    float4 s = sp[tid];
    const float4 m = mp[tid];
    s.x = rna_f(fmaf(gv, m.x, s.x)); s.y = rna_f(fmaf(gv, m.y, s.y));
    s.z = rna_f(fmaf(gv, m.z, s.z)); s.w = rna_f(fmaf(gv, m.w, s.w));
    sp[tid] = s;
}

// ---------------- launcher ----------------
extern "C" void kernel_launch(void* const* d_in, const int* in_sizes, int n_in,
                              void* d_out, int out_size)
{
    const float* x            = (const float*)d_in[0];
    const float* ln1_g        = (const float*)d_in[1];
    const float* ln1_b        = (const float*)d_in[2];
    const float* qkv_w        = (const float*)d_in[3];
    const float* qkv_b        = (const float*)d_in[4];
    const float* w1w          = (const float*)d_in[5];
    const float* w2w          = (const float*)d_in[6];
    const float* w1r          = (const float*)d_in[7];
    const float* w2r          = (const float*)d_in[8];
    const float* memv_w       = (const float*)d_in[9];
    const float* memv_b       = (const float*)d_in[10];
    const float* memg_w       = (const float*)d_in[11];
    const float* memg_b       = (const float*)d_in[12];
    const float* mem_scale    = (const float*)d_in[13];
    const float* out_w        = (const float*)d_in[14];
    const float* out_b        = (const float*)d_in[15];
    const float* decay_logits = (const float*)d_in[16];
    const float* ln2_g        = (const float*)d_in[17];
    const float* ln2_b        = (const float*)d_in[18];
    const float* fc1_w        = (const float*)d_in[19];
    const float* fc1_b        = (const float*)d_in[20];
    const float* fc2_w        = (const float*)d_in[21];
    const float* fc2_b        = (const float*)d_in[22];
    float* out = (float*)d_out;

    float *ph, *pqkv, *psmall, *pseq, *px2, *ph2, *pff1;
    cudaGetSymbolAddress((void**)&ph,     g_h);
    cudaGetSymbolAddress((void**)&pqkv,   g_qkv);
    cudaGetSymbolAddress((void**)&psmall, g_small);
    cudaGetSymbolAddress((void**)&pseq,   g_seq);
    cudaGetSymbolAddress((void**)&px2,    g_x2);
    cudaGetSymbolAddress((void**)&ph2,    g_h2);
    cudaGetSymbolAddress((void**)&pff1,   g_ff1);
    float *pwcat, *pbcat, *pwqkv, *pbqkvm, *pwout, *pwfc1, *pwfc2;
    cudaGetSymbolAddress((void**)&pwcat,  g_wcat);
    cudaGetSymbolAddress((void**)&pbcat,  g_bcat);
    cudaGetSymbolAddress((void**)&pwqkv,  g_wqkv);
    cudaGetSymbolAddress((void**)&pbqkvm, g_bqkvm);
    cudaGetSymbolAddress((void**)&pwout,  g_wout);
    cudaGetSymbolAddress((void**)&pwfc1,  g_wfc1);
    cudaGetSymbolAddress((void**)&pwfc2,  g_wfc2);

    cudaFuncSetAttribute(tgemm_kernel<EPI_BIAS,1>,      cudaFuncAttributeMaxDynamicSharedMemorySize, TG_SMEM);
    cudaFuncSetAttribute(tgemm_kernel<EPI_BIAS_RES,0>,  cudaFuncAttributeMaxDynamicSharedMemorySize, TG_SMEM);
    cudaFuncSetAttribute(tgemm_kernel<EPI_BIAS_GELU,1>, cudaFuncAttributeMaxDynamicSharedMemorySize, TG_SMEM);
    cudaFuncSetAttribute(attn_mma_kernel,               cudaFuncAttributeMaxDynamicSharedMemorySize, ATTN_SMEM);

    // (1) roundw (2) ln1 (3) qkv (4) attn <- profiled
    roundw_all_kernel<<<(N4_TOT+255)/256, 256>>>((const float4*)qkv_w, (const float4*)memv_w,
                                                 (const float4*)out_w, (const float4*)fc1_w,
                                                 (const float4*)fc2_w, (const float4*)qkv_b,
                                                 (const float4*)memv_b);
    ln_kernel<<<Mrows, 256>>>(x, ln1_g, ln1_b, ph);

    // merged qkv+memval: [4096, 4096]
    tgemm_kernel<EPI_BIAS,1><<<dim3(32,32), 256, TG_SMEM>>>(ph, pwqkv, pbqkvm, nullptr, pqkv, Mrows, QKVN, Dm);

    attn_mma_kernel<<<dim3(Tn/64, Bsz*Hn), 128, ATTN_SMEM>>>();

    wcat_kernel<<<NSMALL, 256>>>(w1w, w2w, w1r, w2r, memg_w, memg_b);
    pow_kernel<<<Hn, 256>>>(decay_logits);
    sgemm_small_kernel<<<dim3(3,32), 256>>>(ph, pwcat, pbcat, psmall, Mrows, NSMALL, Dm);
    lines_kernel<<<Mrows*Hn/256, 256>>>();
    mscore_kernel<<<dim3(Bsz*Hn, Tn/256), 256>>>();
    gatedfuse_kernel<<<Mrows, 256>>>(mem_scale);

    // out proj + residual x -> x2
    tgemm_kernel<EPI_BIAS_RES,0><<<dim3(8,32), 256, TG_SMEM>>>(pseq, pwout, out_b, x, px2, Mrows, Dm, Dm);
    // LN2
    ln_kernel<<<Mrows, 256>>>(px2, ln2_g, ln2_b, ph2);
    // fc1 + gelu (tf32): [4096,4096]
    tgemm_kernel<EPI_BIAS_GELU,1><<<dim3(32,32), 256, TG_SMEM>>>(ph2, pwfc1, fc1_b, nullptr, pff1, Mrows, DFFn, Dm);
    // fc2 + bias + residual (tf32) -> out
    tgemm_kernel<EPI_BIAS_RES,0><<<dim3(8,32), 256, TG_SMEM>>>(pff1, pwfc2, fc2_b, px2, out, Mrows, Dm, DFFn);
}

// round 16
// speedup vs baseline: 1.0185x; 1.0185x over previous
#include <cuda_runtime.h>
#include <math.h>
#include <stdint.h>

#define Bsz   4
#define Tn    1024
#define Dm    1024
#define Hn    16
#define Mrows (Bsz*Tn)
#define DFFn  4096
#define NSMALL 272
#define QKVN  4096   // qkv(3072) + memval(1024) merged

__device__ float g_h     [Mrows*Dm];
__device__ float g_qkv   [Mrows*QKVN];
__device__ float g_small [Mrows*NSMALL];
__device__ float g_seq   [Mrows*Dm];
__device__ float g_jw    [Bsz*Hn*Tn*8];
__device__ float g_rl    [Bsz*Hn*Tn*6];
__device__ float g_mscore[Bsz*Hn*Tn];
__device__ float g_x2    [Mrows*Dm];
__device__ float g_h2    [Mrows*Dm];
__device__ float g_ff1   [Mrows*DFFn];
__device__ float g_powd  [Hn*Tn];
__device__ float g_wcat  [NSMALL*Dm];
__device__ float g_bcat  [NSMALL];
__device__ float g_wqkv  [4*Dm*Dm];
__device__ float g_bqkvm [QKVN];
__device__ float g_wout  [Dm*Dm];
__device__ float g_wfc1  [DFFn*Dm];
__device__ float g_wfc2  [Dm*DFFn];

__device__ __forceinline__ float sigf(float x){ return 1.f/(1.f+__expf(-x)); }
__device__ __forceinline__ float geluf(float v){
    return 0.5f*v*(1.f + erff(v*0.7071067811865476f));
}
__device__ __forceinline__ uint32_t rna_u(uint32_t x){
    uint32_t r; asm("cvt.rna.tf32.f32 %0, %1;" : "=r"(r) : "r"(x)); return r;
}
__device__ __forceinline__ float rna_f(float x){
    return __uint_as_float(rna_u(__float_as_uint(x)));
}
__device__ __forceinline__ void mma_tf32(float* d, const uint32_t* a, const uint32_t* b){
    asm volatile("mma.sync.aligned.m16n8k8.row.col.f32.tf32.tf32.f32 "
        "{%0,%1,%2,%3}, {%4,%5,%6,%7}, {%8,%9}, {%0,%1,%2,%3};"
        : "+f"(d[0]), "+f"(d[1]), "+f"(d[2]), "+f"(d[3])
        : "r"(a[0]), "r"(a[1]), "r"(a[2]), "r"(a[3]), "r"(b[0]), "r"(b[1]));
}
__device__ __forceinline__ void cpa16(uint32_t dst, const void* src){
    asm volatile("cp.async.cg.shared.global [%0], [%1], 16;" :: "r"(dst), "l"(src) : "memory");
}
__device__ __forceinline__ void cpa_commit(){
    asm volatile("cp.async.commit_group;" ::: "memory");
}
template<int N>
__device__ __forceinline__ void cpa_wait(){
    asm volatile("cp.async.wait_group %0;" :: "n"(N) : "memory");
}
__device__ __forceinline__ int fwz(int r, int gi, int off){
    return r*64 + ((((gi ^ r) & 7) | (gi & 8)) << 2) + off;
}

// ---------------- merged weight tf32 pre-round + bias concat ----------------
#define N4_QKV  (3*Dm*Dm/4)
#define N4_DM   (Dm*Dm/4)
#define N4_FF   (DFFn*Dm/4)
#define N4_BIAS (QKVN/4)
#define N4_TOT  (N4_QKV + 2*N4_DM + 2*N4_FF + N4_BIAS)
__global__ __launch_bounds__(256) void roundw_all_kernel(
    const float4* __restrict__ qkv_w, const float4* __restrict__ memv_w,
    const float4* __restrict__ out_w, const float4* __restrict__ fc1_w,
    const float4* __restrict__ fc2_w, const float4* __restrict__ qkv_b,
    const float4* __restrict__ memv_b)
{
    const int i = blockIdx.x*256 + threadIdx.x;
    if (i >= N4_TOT) return;
    int k = i;
    const float4* src; float4* dst;
    if      (k < N4_QKV){ src=qkv_w; dst=(float4*)g_wqkv; }
    else if ((k -= N4_QKV) < N4_DM){ src=memv_w; dst=(float4*)g_wqkv + N4_QKV; }
    else if ((k -= N4_DM)  < N4_DM){ src=out_w;  dst=(float4*)g_wout; }
    else if ((k -= N4_DM)  < N4_FF){ src=fc1_w;  dst=(float4*)g_wfc1; }
    else if ((k -= N4_FF)  < N4_FF){ src=fc2_w;  dst=(float4*)g_wfc2; }
    else {
        k -= N4_FF;
        ((float4*)g_bqkvm)[k] = (k < 3*Dm/4) ? qkv_b[k] : memv_b[k - 3*Dm/4];
        return;
    }
    float4 v = src[k];
    v.x=rna_f(v.x); v.y=rna_f(v.y); v.z=rna_f(v.z); v.w=rna_f(v.w);
    dst[k] = v;
}

// ============================================================================
// tf32 GEMM — R11 proven: CTA 128x128, 256 thr / 8 warps, warp 32x64,
// K-chunk 32, cp.async 3-stage (96KB), 2 CTAs/SM.
// ============================================================================
enum { EPI_BIAS=0, EPI_BIAS_RES=1, EPI_BIAS_GELU=2 };

template<int EPI, int RND>
__global__ __launch_bounds__(256, 2) void tgemm_kernel(
    const float* __restrict__ A, const float* __restrict__ W,
    const float* __restrict__ bias, const float* __restrict__ res,
    float* __restrict__ C, int M, int N, int K)
{
    extern __shared__ uint32_t sm[];
    const uint32_t smb = (uint32_t)__cvta_generic_to_shared(sm);

    const int tid  = threadIdx.x;
    const int lane = tid & 31;
    const int warp = tid >> 5;
    const int g    = lane >> 2;
    const int tig  = lane & 3;
    const int wm   = (warp & 3) * 32;
    const int wn   = (warp >> 2) * 64;
    const int bm   = blockIdx.y * 128;
    const int bn   = blockIdx.x * 128;

    float acc[2][8][4];
    #pragma unroll
    for (int i=0;i<2;i++)
        #pragma unroll
        for (int j=0;j<8;j++)
            #pragma unroll
            for (int c=0;c<4;c++) acc[i][j][c]=0.f;

    const int r = tid >> 3;
    const int q = tid & 7;
    const int nchunks = K >> 5;

    int istage = 0;
    auto issue = [&](int i){
        const uint32_t aB = smb + (uint32_t)istage*32768u;
        const uint32_t bB = aB + 16384u;
        istage = (istage == 2) ? 0 : istage + 1;
        const int kofs = i << 5;
        #pragma unroll
        for (int it = 0; it < 4; it++){
            const int rr = r + it*32;
            const uint32_t off = ((uint32_t)rr*32u + (uint32_t)((q ^ (rr & 7)) << 2)) * 4u;
            cpa16(aB + off, &A[(size_t)(bm + rr)*K + kofs + q*4]);
            cpa16(bB + off, &W[(size_t)(bn + rr)*K + kofs + q*4]);
        }
        cpa_commit();
    };

    issue(0);
    if (nchunks > 1) issue(1);

    int cstage = 0;
    for (int i = 0; i < nchunks; i++){
        if (i + 2 < nchunks){ issue(i + 2); cpa_wait<2>(); }
        else if (i + 1 < nchunks) cpa_wait<1>();
        else cpa_wait<0>();
        __syncthreads();

        const uint32_t* As = sm + (size_t)cstage*8192;
        const uint32_t* Bs = As + 4096;
        cstage = (cstage == 2) ? 0 : cstage + 1;

        #pragma unroll
        for (int ks = 0; ks < 4; ks++){
            uint32_t af[2][4];
            #pragma unroll
            for (int ii = 0; ii < 2; ii++){
                const int m  = wm + ii*16 + g;
                const int g0 = ((2*ks)   ^ (m & 7)) << 2;
                const int g1 = ((2*ks+1) ^ (m & 7)) << 2;
                af[ii][0] = As[m*32     + g0 + tig];
                af[ii][1] = As[(m+8)*32 + g0 + tig];
                af[ii][2] = As[m*32     + g1 + tig];
                af[ii][3] = As[(m+8)*32 + g1 + tig];
            }
            uint32_t bf[8][2];
            #pragma unroll
            for (int j = 0; j < 8; j++){
                const int n  = wn + j*8 + g;
                const int g0 = ((2*ks)   ^ (n & 7)) << 2;
                const int g1 = ((2*ks+1) ^ (n & 7)) << 2;
                bf[j][0] = Bs[n*32 + g0 + tig];
                bf[j][1] = Bs[n*32 + g1 + tig];
            }
            #pragma unroll
            for (int ii = 0; ii < 2; ii++)
                #pragma unroll
                for (int j = 0; j < 8; j++)
                    mma_tf32(acc[ii][j], af[ii], bf[j]);
        }
        __syncthreads();
    }

    #pragma unroll
    for (int i = 0; i < 2; i++){
        const int row = bm + wm + i*16 + g;
        #pragma unroll
        for (int j = 0; j < 8; j++){
            const int col = bn + wn + j*8 + tig*2;
            const float b0 = bias[col], b1 = bias[col+1];
            float v0 = acc[i][j][0] + b0;
            float v1 = acc[i][j][1] + b1;
            float v2 = acc[i][j][2] + b0;
            float v3 = acc[i][j][3] + b1;
            if (EPI == EPI_BIAS_GELU){
                v0=geluf(v0); v1=geluf(v1); v2=geluf(v2); v3=geluf(v3);
            } else if (EPI == EPI_BIAS_RES){
                const float2 r0 = *reinterpret_cast<const float2*>(&res[(size_t)row*N + col]);
                const float2 r1 = *reinterpret_cast<const float2*>(&res[(size_t)(row+8)*N + col]);
                v0+=r0.x; v1+=r0.y; v2+=r1.x; v3+=r1.y;
            }
            if (RND){
                v0=rna_f(v0); v1=rna_f(v1); v2=rna_f(v2); v3=rna_f(v3);
            }
            *reinterpret_cast<float2*>(&C[(size_t)row*N + col])     = make_float2(v0,v1);
            *reinterpret_cast<float2*>(&C[(size_t)(row+8)*N + col]) = make_float2(v2,v3);
        }
    }
}
#define TG_SMEM (3*8192*4)

// ============================================================================
// tf32 flash attention: Q-tile 128 (256 thr, 8 warps x 16 q-rows), KV tile 64,
// SINGLE-stage KV -> smem = Q 32K + P 32K + K 16K + V 16K = 96KB
// -> 2 CTAs/SM = 16 warps (regs capped 128 via launch_bounds).
// LPT: qt = 7 - blockIdx.x. Grid (8, B*H).
// smem words: Q @0 (8192), P @8192 (8192), K @16384 (4096), V @20480 (4096).
// ============================================================================
#define AQ_OFF 0
#define AP_OFF 8192
#define AK_OFF 16384
#define AV_OFF 20480
#define ATTN_SMEM (24576*4)

__global__ __launch_bounds__(256, 2) void attn_mma_kernel()
{
    extern __shared__ uint32_t smA[];
    const uint32_t smb = (uint32_t)__cvta_generic_to_shared(smA);
    const int tid  = threadIdx.x;
    const int lane = tid & 31;
    const int warp = tid >> 5;
    const int g    = lane >> 2;
    const int tig  = lane & 3;
    const int wm   = warp * 16;                    // 0..112
    const int qt   = (Tn/128 - 1) - blockIdx.x;    // heavy tiles first
    const int bh   = blockIdx.y;
    const int b    = bh >> 4, h = bh & 15;
    const int nkt  = 2*qt + 2;                     // KV tiles of 64

    // Q tile: 128 rows, 2 threads per row x 8 granules
    {
        const int lr  = tid >> 1;
        const int lg0 = (tid & 1) * 8;
        const float* src = &g_qkv[((size_t)(b*Tn + qt*128 + lr))*QKVN + h*64];
        #pragma unroll
        for (int i = 0; i < 8; i++){
            const int gi = lg0 + i;
            const int gs = ((gi ^ (lr & 7)) & 7) | (gi & 8);
            cpa16(smb + (uint32_t)(AQ_OFF + lr*64 + gs*4)*4u, src + gi*4);
        }
        cpa_commit();
    }
    // KV tile: 64 rows, 4 threads per row x 4 granules
    auto issueKV = [&](int kt){
        const int kr  = tid >> 2;
        const int kg0 = (tid & 3) * 4;
        const float* srcK = &g_qkv[((size_t)(b*Tn + kt*64 + kr))*QKVN + 1024 + h*64];
        #pragma unroll
        for (int i = 0; i < 4; i++){
            const int gi = kg0 + i;
            const int gs = ((gi ^ (kr & 7)) & 7) | (gi & 8);
            const uint32_t woff = (uint32_t)(kr*64 + gs*4);
            cpa16(smb + (uint32_t)(AK_OFF + woff)*4u, srcK + gi*4);
            cpa16(smb + (uint32_t)(AV_OFF + woff)*4u, srcK + 1024 + gi*4);
        }
        cpa_commit();
    };
    issueKV(0);

    float M0=-1e30f, M1=-1e30f, L0=0.f, L1=0.f;
    float o[8][4];
    #pragma unroll
    for (int j=0;j<8;j++)
        #pragma unroll
        for (int c=0;c<4;c++) o[j][c]=0.f;

    const uint32_t* Qs = smA + AQ_OFF;
    uint32_t* Ps = smA + AP_OFF;
    const uint32_t* Ks = smA + AK_OFF;
    const uint32_t* Vs = smA + AV_OFF;

    for (int kt = 0; kt < nkt; kt++){
        cpa_wait<0>();
        __syncthreads();          // KV[kt] visible

        float s[8][4];
        #pragma unroll
        for (int j=0;j<8;j++)
            #pragma unroll
            for (int c=0;c<4;c++) s[j][c]=0.f;

        #pragma unroll
        for (int ks = 0; ks < 8; ks++){
            uint32_t a[4];
            const int m = wm + g;
            a[0] = Qs[fwz(m,   2*ks,   tig)];
            a[1] = Qs[fwz(m+8, 2*ks,   tig)];
            a[2] = Qs[fwz(m,   2*ks+1, tig)];
            a[3] = Qs[fwz(m+8, 2*ks+1, tig)];
            #pragma unroll
            for (int j = 0; j < 8; j++){
                uint32_t bfr[2];
                const int n = 8*j + g;
                bfr[0] = Ks[fwz(n, 2*ks,   tig)];
                bfr[1] = Ks[fwz(n, 2*ks+1, tig)];
                mma_tf32(s[j], a, bfr);
            }
        }

        // scale + causal mask on the (up to) two diagonal tiles
        const bool maybe_mask = (kt >= 2*qt);
        const int gr0 = qt*128 + wm + g;
        const int gr1 = gr0 + 8;
        #pragma unroll
        for (int j = 0; j < 8; j++){
            float v0 = s[j][0]*0.125f, v1 = s[j][1]*0.125f;
            float v2 = s[j][2]*0.125f, v3 = s[j][3]*0.125f;
            if (maybe_mask){
                const int c0 = kt*64 + 8*j + 2*tig, c1 = c0 + 1;
                if (c0 > gr0) v0 = -1e30f;
                if (c1 > gr0) v1 = -1e30f;
                if (c0 > gr1) v2 = -1e30f;
                if (c1 > gr1) v3 = -1e30f;
            }
            s[j][0]=v0; s[j][1]=v1; s[j][2]=v2; s[j][3]=v3;
        }

        float tm0 = -1e30f, tm1 = -1e30f;
        #pragma unroll
        for (int j = 0; j < 8; j++){
            tm0 = fmaxf(tm0, fmaxf(s[j][0], s[j][1]));
            tm1 = fmaxf(tm1, fmaxf(s[j][2], s[j][3]));
        }
        tm0 = fmaxf(tm0, __shfl_xor_sync(0xffffffffu, tm0, 1));
        tm0 = fmaxf(tm0, __shfl_xor_sync(0xffffffffu, tm0, 2));
        tm1 = fmaxf(tm1, __shfl_xor_sync(0xffffffffu, tm1, 1));
        tm1 = fmaxf(tm1, __shfl_xor_sync(0xffffffffu, tm1, 2));
        const float Mn0 = fmaxf(M0, tm0), Mn1 = fmaxf(M1, tm1);
        const float f0 = __expf(M0 - Mn0), f1 = __expf(M1 - Mn1);
        float ps0 = 0.f, ps1 = 0.f;
        #pragma unroll
        for (int j = 0; j < 8; j++){
            const float p0 = __expf(s[j][0] - Mn0);
            const float p1 = __expf(s[j][1] - Mn0);
            const float p2 = __expf(s[j][2] - Mn1);
            const float p3 = __expf(s[j][3] - Mn1);
            ps0 += p0 + p1; ps1 += p2 + p3;
            const int c = 8*j + 2*tig;
            const int gi = c >> 2, off = c & 3;
            uint32_t* p01 = &Ps[fwz(wm+g,   gi, off)];
            uint32_t* p23 = &Ps[fwz(wm+g+8, gi, off)];
            p01[0] = rna_u(__float_as_uint(p0)); p01[1] = rna_u(__float_as_uint(p1));
            p23[0] = rna_u(__float_as_uint(p2)); p23[1] = rna_u(__float_as_uint(p3));
            o[j][0] *= f0; o[j][1] *= f0; o[j][2] *= f1; o[j][3] *= f1;
        }
        ps0 += __shfl_xor_sync(0xffffffffu, ps0, 1);
        ps0 += __shfl_xor_sync(0xffffffffu, ps0, 2);
        ps1 += __shfl_xor_sync(0xffffffffu, ps1, 1);
        ps1 += __shfl_xor_sync(0xffffffffu, ps1, 2);
        L0 = L0*f0 + ps0; L1 = L1*f1 + ps1;
        M0 = Mn0; M1 = Mn1;
        __syncwarp();

        #pragma unroll
        for (int kk = 0; kk < 8; kk++){
            uint32_t a[4];
            const int m = wm + g;
            a[0] = Ps[fwz(m,   2*kk,   tig)];
            a[1] = Ps[fwz(m+8, 2*kk,   tig)];
            a[2] = Ps[fwz(m,   2*kk+1, tig)];
            a[3] = Ps[fwz(m+8, 2*kk+1, tig)];
            #pragma unroll
            for (int j = 0; j < 8; j++){
                uint32_t bfr[2];
                const int n = 8*j + g;
                const int gi = n >> 2, off = n & 3;
                bfr[0] = Vs[fwz(8*kk + tig,     gi, off)];
                bfr[1] = Vs[fwz(8*kk + 4 + tig, gi, off)];
                mma_tf32(o[j], a, bfr);
            }
        }
        __syncthreads();          // all warps done reading K/V[kt]
        if (kt + 1 < nkt) issueKV(kt + 1);
    }

    const float i0 = 1.f / L0, i1 = 1.f / L1;
    const int r0 = b*Tn + qt*128 + wm + g;
    #pragma unroll
    for (int j = 0; j < 8; j++){
        const int col = h*64 + 8*j + 2*tig;
        *reinterpret_cast<float2*>(&g_seq[(size_t)r0*Dm + col]) =
            make_float2(o[j][0]*i0, o[j][1]*i0);
        *reinterpret_cast<float2*>(&g_seq[(size_t)(r0+8)*Dm + col]) =
            make_float2(o[j][2]*i1, o[j][3]*i1);
    }
}

// ---------------- LayerNorm (tf32-rounded out) ----------------
__global__ __launch_bounds__(256) void ln_kernel(const float* __restrict__ x,
    const float* __restrict__ g, const float* __restrict__ b, float* __restrict__ out)
{
    const int row = blockIdx.x;
    const int tid = threadIdx.x;
    const float4 v = reinterpret_cast<const float4*>(x + (size_t)row*Dm)[tid];
    float s  = v.x+v.y+v.z+v.w;
    float s2 = v.x*v.x+v.y*v.y+v.z*v.z+v.w*v.w;
    #pragma unroll
    for (int off=16; off>0; off>>=1){
        s  += __shfl_xor_sync(0xffffffffu, s,  off);
        s2 += __shfl_xor_sync(0xffffffffu, s2, off);
    }
    __shared__ float ss[8], ss2[8];
    if ((tid & 31)==0){ ss[tid>>5]=s; ss2[tid>>5]=s2; }
    __syncthreads();
    float ts=0.f, ts2=0.f;
    #pragma unroll
    for (int i=0;i<8;i++){ ts+=ss[i]; ts2+=ss2[i]; }
    const float mu  = ts*(1.f/1024.f);
    const float inv = rsqrtf(ts2*(1.f/1024.f) - mu*mu + 1e-5f);
    const float4 gv = reinterpret_cast<const float4*>(g)[tid];
    const float4 bv = reinterpret_cast<const float4*>(b)[tid];
    float4 o;
    o.x=rna_f((v.x-mu)*inv*gv.x+bv.x); o.y=rna_f((v.y-mu)*inv*gv.y+bv.y);
    o.z=rna_f((v.z-mu)*inv*gv.z+bv.z); o.w=rna_f((v.w-mu)*inv*gv.w+bv.w);
    reinterpret_cast<float4*>(out + (size_t)row*Dm)[tid] = o;
}

// ---------------- concat small weights ----------------
__global__ __launch_bounds__(256) void wcat_kernel(
    const float* __restrict__ w1w, const float* __restrict__ w2w,
    const float* __restrict__ w1r, const float* __restrict__ w2r,
    const float* __restrict__ memg_w, const float* __restrict__ memg_b)
{
    const int r = blockIdx.x;
    const float* src;
    if      (r < 64)  src = w1w + (size_t)r*Dm;
    else if (r < 128) src = w2w + (size_t)(r-64)*Dm;
    else if (r < 192) src = w1r + (size_t)(r-128)*Dm;
    else if (r < 256) src = w2r + (size_t)(r-192)*Dm;
    else              src = memg_w + (size_t)(r-256)*Dm;
    reinterpret_cast<float4*>(g_wcat + (size_t)r*Dm)[threadIdx.x] =
        reinterpret_cast<const float4*>(src)[threadIdx.x];
    if (r == 0){
        for (int c = threadIdx.x; c < NSMALL; c += 256)
            g_bcat[c] = (c < 256) ? 0.f : memg_b[c-256];
    }
}

// ---------------- fp32 SGEMM for the 272-col small projection ----------------
__global__ __launch_bounds__(256) void sgemm_small_kernel(
    const float* __restrict__ A, const float* __restrict__ W,
    const float* __restrict__ bias, float* __restrict__ C, int M, int N, int K)
{
    __shared__ float As[16][128];
    __shared__ float Ws[16][128];
    const int tid = threadIdx.x;
    const int bm  = blockIdx.y * 128;
    const int bn  = blockIdx.x * 128;
    const int ty  = tid >> 4;
    const int tx  = tid & 15;
    const int lr  = tid >> 2;
    const int lk  = (tid & 3) << 2;

    float acc[8][8];
    #pragma unroll
    for (int i=0;i<8;i++)
        #pragma unroll
        for (int j=0;j<8;j++) acc[i][j]=0.f;

    for (int k0 = 0; k0 < K; k0 += 16){
        #pragma unroll
        for (int it=0; it<2; it++){
            const int r = lr + it*64;
            const float4 a = *reinterpret_cast<const float4*>(&A[(size_t)(bm + r)*K + k0 + lk]);
            As[lk+0][r]=a.x; As[lk+1][r]=a.y; As[lk+2][r]=a.z; As[lk+3][r]=a.w;
        }
        #pragma unroll
        for (int it=0; it<2; it++){
            const int r = lr + it*64;
            const int n = bn + r;
            float4 w = make_float4(0.f,0.f,0.f,0.f);
            if (n < N) w = *reinterpret_cast<const float4*>(&W[(size_t)n*K + k0 + lk]);
            Ws[lk+0][r]=w.x; Ws[lk+1][r]=w.y; Ws[lk+2][r]=w.z; Ws[lk+3][r]=w.w;
        }
        __syncthreads();
        #pragma unroll
        for (int kk=0; kk<16; kk++){
            float ar[8], wr[8];
            *reinterpret_cast<float4*>(&ar[0]) = *reinterpret_cast<const float4*>(&As[kk][ty*4]);
            *reinterpret_cast<float4*>(&ar[4]) = *reinterpret_cast<const float4*>(&As[kk][ty*4+64]);
            *reinterpret_cast<float4*>(&wr[0]) = *reinterpret_cast<const float4*>(&Ws[kk][tx*4]);
            *reinterpret_cast<float4*>(&wr[4]) = *reinterpret_cast<const float4*>(&Ws[kk][tx*4+64]);
            #pragma unroll
            for (int i=0;i<8;i++)
                #pragma unroll
                for (int j=0;j<8;j++)
                    acc[i][j] = fmaf(ar[i], wr[j], acc[i][j]);
        }
        __syncthreads();
    }

    #pragma unroll
    for (int i=0;i<8;i++){
        const int m = bm + ty*4 + ((i<4) ? i : 64 + (i-4));
        #pragma unroll
        for (int jb=0; jb<2; jb++){
            const int n = bn + tx*4 + jb*64;
            if (n < N){
                float v0=acc[i][jb*4+0]+bias[n],   v1=acc[i][jb*4+1]+bias[n+1];
                float v2=acc[i][jb*4+2]+bias[n+2], v3=acc[i][jb*4+3]+bias[n+3];
                *reinterpret_cast<float4*>(&C[(size_t)m*N + n]) = make_float4(v0,v1,v2,v3);
            }
        }
    }
}

// ---------------- Plucker lines + J permutation ----------------
__global__ __launch_bounds__(256) void lines_kernel()
{
    const int idx = blockIdx.x*256 + threadIdx.x;
    const int row = idx >> 4;
    const int h   = idx & 15;
    const int b   = row >> 10;
    const int t   = row & 1023;
    const float* s = g_small + (size_t)row*NSMALL;

    float p1[4], p2[4], L[6];
    if (t == 0){ p1[0]=p1[1]=p1[2]=p1[3]=0.f; }
    else {
        const float* sp = s - NSMALL;
        #pragma unroll
        for (int p=0;p<4;p++) p1[p] = sp[h*4+p];
    }
    #pragma unroll
    for (int p=0;p<4;p++) p2[p] = s[64 + h*4 + p];

    L[0]=p1[0]*p2[1]-p1[1]*p2[0];
    L[1]=p1[0]*p2[2]-p1[2]*p2[0];
    L[2]=p1[0]*p2[3]-p1[3]*p2[0];
    L[3]=p1[1]*p2[2]-p1[2]*p2[1];
    L[4]=p1[1]*p2[3]-p1[3]*p2[1];
    L[5]=p1[2]*p2[3]-p1[3]*p2[2];
    float nn = sqrtf(L[0]*L[0]+L[1]*L[1]+L[2]*L[2]+L[3]*L[3]+L[4]*L[4]+L[5]*L[5]);
    float inv = 1.f / fmaxf(nn, 1e-12f);
    float* jw = &g_jw[(((size_t)(b*Hn+h))*Tn + t)*8];
    jw[0]= L[5]*inv; jw[1]=-L[4]*inv; jw[2]= L[3]*inv;
    jw[3]= L[2]*inv; jw[4]=-L[1]*inv; jw[5]= L[0]*inv;
    jw[6]=0.f; jw[7]=0.f;

    #pragma unroll
    for (int p=0;p<4;p++){ p1[p]=s[128+h*4+p]; p2[p]=s[192+h*4+p]; }
    L[0]=p1[0]*p2[1]-p1[1]*p2[0];
    L[1]=p1[0]*p2[2]-p1[2]*p2[0];
    L[2]=p1[0]*p2[3]-p1[3]*p2[0];
    L[3]=p1[1]*p2[2]-p1[2]*p2[1];
    L[4]=p1[1]*p2[3]-p1[3]*p2[1];
    L[5]=p1[2]*p2[3]-p1[3]*p2[2];
    nn = sqrtf(L[0]*L[0]+L[1]*L[1]+L[2]*L[2]+L[3]*L[3]+L[4]*L[4]+L[5]*L[5]);
    inv = 1.f / fmaxf(nn, 1e-12f);
    float* rl = &g_rl[(((size_t)(b*Hn+h))*Tn + t)*6];
    #pragma unroll
    for (int p=0;p<6;p++) rl[p] = L[p]*inv;
}

// ---------------- decay^delta table ----------------
__global__ void pow_kernel(const float* __restrict__ decay_logits)
{
    const int h = blockIdx.x;
    const float d  = 1.f/(1.f+expf(-decay_logits[h]));
    const float l2 = log2f(d);
    for (int t = threadIdx.x; t < Tn; t += blockDim.x)
        g_powd[h*Tn + t] = exp2f((float)t * l2);
}

// ---------------- mem_score: grid (bh, 4 q-chunks of 256) ----------------
__global__ __launch_bounds__(256) void mscore_kernel()
{
    const int bh = blockIdx.x;
    const int qc = blockIdx.y;
    const int h  = bh & 15;
    const int jmax = (qc + 1) * 256;
    __shared__ float jw_s[Tn*8];
    __shared__ float pw_s[Tn];
    const int tid = threadIdx.x;
    for (int i = tid; i < jmax*2; i += 256)
        reinterpret_cast<float4*>(jw_s)[i] =
            reinterpret_cast<const float4*>(g_jw + (size_t)bh*Tn*8)[i];
    for (int i = tid; i < Tn; i += 256) pw_s[i] = g_powd[h*Tn + i];
    __syncthreads();

    const int q = qc*256 + tid;
    float r0,r1,r2,r3,r4,r5;
    const float* rp = &g_rl[((size_t)bh*Tn + q)*6];
    r0=rp[0]; r1=rp[1]; r2=rp[2]; r3=rp[3]; r4=rp[4]; r5=rp[5];
    float acc = 0.f;
    for (int j = 0; j < q; j++){
        const float2 w0 = *reinterpret_cast<const float2*>(&jw_s[j*8+0]);
        const float2 w1 = *reinterpret_cast<const float2*>(&jw_s[j*8+2]);
        const float2 w2 = *reinterpret_cast<const float2*>(&jw_s[j*8+4]);
        float dot = r0*w0.x;
        dot = fmaf(r1, w0.y, dot);
        dot = fmaf(r2, w1.x, dot);
        dot = fmaf(r3, w1.y, dot);
        dot = fmaf(r4, w2.x, dot);
        dot = fmaf(r5, w2.y, dot);
        acc = fmaf(fabsf(dot), pw_s[q-j], acc);
    }
    g_mscore[(size_t)bh*Tn + q] = acc;
}

// ---------------- gated+fuse merged ----------------
__global__ __launch_bounds__(256) void gatedfuse_kernel(const float* __restrict__ mem_scale)
{
    const int row = blockIdx.x;
    const int b = row >> 10, t = row & 1023;
    const int tid = threadIdx.x;
    __shared__ float gv_s;
    if (tid < 16){
        const float ms = g_mscore[(size_t)(b*Hn+tid)*Tn + t];
        const float gt = sigf(g_small[(size_t)row*NSMALL + 256 + tid]);
        float v = sigf(ms * mem_scale[tid]) * gt;
        v += __shfl_xor_sync(0xffffu, v, 1, 16);
        v += __shfl_xor_sync(0xffffu, v, 2, 16);
        v += __shfl_xor_sync(0xffffu, v, 4, 16);
        v += __shfl_xor_sync(0xffffu, v, 8, 16);
        if (tid == 0) gv_s = v * (1.f/16.f);
    }
    __syncthreads();
    const float gv = gv_s;
    float4* sp = reinterpret_cast<float4*>(&g_seq[(size_t)row*Dm]);
    const float4* mp = reinterpret_cast<const float4*>(&g_qkv[(size_t)row*QKVN + 3072]);
    float4 s = sp[tid];
    const float4 m = mp[tid];
    s.x = rna_f(fmaf(gv, m.x, s.x)); s.y = rna_f(fmaf(gv, m.y, s.y));
    s.z = rna_f(fmaf(gv, m.z, s.z)); s.w = rna_f(fmaf(gv, m.w, s.w));
    sp[tid] = s;
}

// ---------------- launcher ----------------
extern "C" void kernel_launch(void* const* d_in, const int* in_sizes, int n_in,
                              void* d_out, int out_size)
{
    const float* x            = (const float*)d_in[0];
    const float* ln1_g        = (const float*)d_in[1];
    const float* ln1_b        = (const float*)d_in[2];
    const float* qkv_w        = (const float*)d_in[3];
    const float* qkv_b        = (const float*)d_in[4];
    const float* w1w          = (const float*)d_in[5];
    const float* w2w          = (const float*)d_in[6];
    const float* w1r          = (const float*)d_in[7];
    const float* w2r          = (const float*)d_in[8];
    const float* memv_w       = (const float*)d_in[9];
    const float* memv_b       = (const float*)d_in[10];
    const float* memg_w       = (const float*)d_in[11];
    const float* memg_b       = (const float*)d_in[12];
    const float* mem_scale    = (const float*)d_in[13];
    const float* out_w        = (const float*)d_in[14];
    const float* out_b        = (const float*)d_in[15];
    const float* decay_logits = (const float*)d_in[16];
    const float* ln2_g        = (const float*)d_in[17];
    const float* ln2_b        = (const float*)d_in[18];
    const float* fc1_w        = (const float*)d_in[19];
    const float* fc1_b        = (const float*)d_in[20];
    const float* fc2_w        = (const float*)d_in[21];
    const float* fc2_b        = (const float*)d_in[22];
    float* out = (float*)d_out;

    float *ph, *pqkv, *psmall, *pseq, *px2, *ph2, *pff1;
    cudaGetSymbolAddress((void**)&ph,     g_h);
    cudaGetSymbolAddress((void**)&pqkv,   g_qkv);
    cudaGetSymbolAddress((void**)&psmall, g_small);
    cudaGetSymbolAddress((void**)&pseq,   g_seq);
    cudaGetSymbolAddress((void**)&px2,    g_x2);
    cudaGetSymbolAddress((void**)&ph2,    g_h2);
    cudaGetSymbolAddress((void**)&pff1,   g_ff1);
    float *pwcat, *pbcat, *pwqkv, *pbqkvm, *pwout, *pwfc1, *pwfc2;
    cudaGetSymbolAddress((void**)&pwcat,  g_wcat);
    cudaGetSymbolAddress((void**)&pbcat,  g_bcat);
    cudaGetSymbolAddress((void**)&pwqkv,  g_wqkv);
    cudaGetSymbolAddress((void**)&pbqkvm, g_bqkvm);
    cudaGetSymbolAddress((void**)&pwout,  g_wout);
    cudaGetSymbolAddress((void**)&pwfc1,  g_wfc1);
    cudaGetSymbolAddress((void**)&pwfc2,  g_wfc2);

    cudaFuncSetAttribute(tgemm_kernel<EPI_BIAS,1>,      cudaFuncAttributeMaxDynamicSharedMemorySize, TG_SMEM);
    cudaFuncSetAttribute(tgemm_kernel<EPI_BIAS_RES,0>,  cudaFuncAttributeMaxDynamicSharedMemorySize, TG_SMEM);
    cudaFuncSetAttribute(tgemm_kernel<EPI_BIAS_GELU,1>, cudaFuncAttributeMaxDynamicSharedMemorySize, TG_SMEM);
    cudaFuncSetAttribute(attn_mma_kernel,               cudaFuncAttributeMaxDynamicSharedMemorySize, ATTN_SMEM);

    // (1) roundw (2) ln1 (3) qkv (4) attn <- profiled
    roundw_all_kernel<<<(N4_TOT+255)/256, 256>>>((const float4*)qkv_w, (const float4*)memv_w,
                                                 (const float4*)out_w, (const float4*)fc1_w,
                                                 (const float4*)fc2_w, (const float4*)qkv_b,
                                                 (const float4*)memv_b);
    ln_kernel<<<Mrows, 256>>>(x, ln1_g, ln1_b, ph);

    // merged qkv+memval: [4096, 4096]
    tgemm_kernel<EPI_BIAS,1><<<dim3(32,32), 256, TG_SMEM>>>(ph, pwqkv, pbqkvm, nullptr, pqkv, Mrows, QKVN, Dm);

    attn_mma_kernel<<<dim3(Tn/128, Bsz*Hn), 256, ATTN_SMEM>>>();

    wcat_kernel<<<NSMALL, 256>>>(w1w, w2w, w1r, w2r, memg_w, memg_b);
    pow_kernel<<<Hn, 256>>>(decay_logits);
    sgemm_small_kernel<<<dim3(3,32), 256>>>(ph, pwcat, pbcat, psmall, Mrows, NSMALL, Dm);
    lines_kernel<<<Mrows*Hn/256, 256>>>();
    mscore_kernel<<<dim3(Bsz*Hn, Tn/256), 256>>>();
    gatedfuse_kernel<<<Mrows, 256>>>(mem_scale);

    // out proj + residual x -> x2
    tgemm_kernel<EPI_BIAS_RES,0><<<dim3(8,32), 256, TG_SMEM>>>(pseq, pwout, out_b, x, px2, Mrows, Dm, Dm);
    // LN2
    ln_kernel<<<Mrows, 256>>>(px2, ln2_g, ln2_b, ph2);
    // fc1 + gelu (tf32): [4096,4096]
    tgemm_kernel<EPI_BIAS_GELU,1><<<dim3(32,32), 256, TG_SMEM>>>(ph2, pwfc1, fc1_b, nullptr, pff1, Mrows, DFFn, Dm);
    // fc2 + bias + residual (tf32) -> out
    tgemm_kernel<EPI_BIAS_RES,0><<<dim3(8,32), 256, TG_SMEM>>>(pff1, pwfc2, fc2_b, px2, out, Mrows, Dm, DFFn);
}

// round 17
// speedup vs baseline: 1.1530x; 1.1321x over previous
#include <cuda_runtime.h>
#include <math.h>
#include <stdint.h>

#define Bsz   4
#define Tn    1024
#define Dm    1024
#define Hn    16
#define Mrows (Bsz*Tn)
#define DFFn  4096
#define NSMALL 272
#define NSP   384    // padded small-proj width (multiple of 128)
#define QKVN  4096   // qkv(3072) + memval(1024) merged

__device__ float g_h     [Mrows*Dm];
__device__ float g_qkv   [Mrows*QKVN];
__device__ float g_small [Mrows*NSP];
__device__ float g_seq   [Mrows*Dm];
__device__ float g_jw    [Bsz*Hn*Tn*8];
__device__ float g_rl    [Bsz*Hn*Tn*6];
__device__ float g_mscore[Bsz*Hn*Tn];
__device__ float g_x2    [Mrows*Dm];
__device__ float g_h2    [Mrows*Dm];
__device__ float g_ff1   [Mrows*DFFn];
__device__ float g_powd  [Hn*Tn];
__device__ float g_wcat  [NSP*Dm];
__device__ float g_bcat  [NSP];
__device__ float g_wqkv  [4*Dm*Dm];
__device__ float g_bqkvm [QKVN];
__device__ float g_wout  [Dm*Dm];
__device__ float g_wfc1  [DFFn*Dm];
__device__ float g_wfc2  [Dm*DFFn];

__device__ __forceinline__ float sigf(float x){ return 1.f/(1.f+__expf(-x)); }
__device__ __forceinline__ float geluf(float v){
    return 0.5f*v*(1.f + erff(v*0.7071067811865476f));
}
__device__ __forceinline__ uint32_t rna_u(uint32_t x){
    uint32_t r; asm("cvt.rna.tf32.f32 %0, %1;" : "=r"(r) : "r"(x)); return r;
}
__device__ __forceinline__ float rna_f(float x){
    return __uint_as_float(rna_u(__float_as_uint(x)));
}
__device__ __forceinline__ void mma_tf32(float* d, const uint32_t* a, const uint32_t* b){
    asm volatile("mma.sync.aligned.m16n8k8.row.col.f32.tf32.tf32.f32 "
        "{%0,%1,%2,%3}, {%4,%5,%6,%7}, {%8,%9}, {%0,%1,%2,%3};"
        : "+f"(d[0]), "+f"(d[1]), "+f"(d[2]), "+f"(d[3])
        : "r"(a[0]), "r"(a[1]), "r"(a[2]), "r"(a[3]), "r"(b[0]), "r"(b[1]));
}
__device__ __forceinline__ void cpa16(uint32_t dst, const void* src){
    asm volatile("cp.async.cg.shared.global [%0], [%1], 16;" :: "r"(dst), "l"(src) : "memory");
}
__device__ __forceinline__ void cpa_commit(){
    asm volatile("cp.async.commit_group;" ::: "memory");
}
template<int N>
__device__ __forceinline__ void cpa_wait(){
    asm volatile("cp.async.wait_group %0;" :: "n"(N) : "memory");
}
__device__ __forceinline__ int fwz(int r, int gi, int off){
    return r*64 + ((((gi ^ r) & 7) | (gi & 8)) << 2) + off;
}

// ---------------- merged weight tf32 pre-round + bias concat ----------------
#define N4_QKV  (3*Dm*Dm/4)
#define N4_DM   (Dm*Dm/4)
#define N4_FF   (DFFn*Dm/4)
#define N4_BIAS (QKVN/4)
#define N4_TOT  (N4_QKV + 2*N4_DM + 2*N4_FF + N4_BIAS)
__global__ __launch_bounds__(256) void roundw_all_kernel(
    const float4* __restrict__ qkv_w, const float4* __restrict__ memv_w,
    const float4* __restrict__ out_w, const float4* __restrict__ fc1_w,
    const float4* __restrict__ fc2_w, const float4* __restrict__ qkv_b,
    const float4* __restrict__ memv_b)
{
    const int i = blockIdx.x*256 + threadIdx.x;
    if (i >= N4_TOT) return;
    int k = i;
    const float4* src; float4* dst;
    if      (k < N4_QKV){ src=qkv_w; dst=(float4*)g_wqkv; }
    else if ((k -= N4_QKV) < N4_DM){ src=memv_w; dst=(float4*)g_wqkv + N4_QKV; }
    else if ((k -= N4_DM)  < N4_DM){ src=out_w;  dst=(float4*)g_wout; }
    else if ((k -= N4_DM)  < N4_FF){ src=fc1_w;  dst=(float4*)g_wfc1; }
    else if ((k -= N4_FF)  < N4_FF){ src=fc2_w;  dst=(float4*)g_wfc2; }
    else {
        k -= N4_FF;
        ((float4*)g_bqkvm)[k] = (k < 3*Dm/4) ? qkv_b[k] : memv_b[k - 3*Dm/4];
        return;
    }
    float4 v = src[k];
    v.x=rna_f(v.x); v.y=rna_f(v.y); v.z=rna_f(v.z); v.w=rna_f(v.w);
    dst[k] = v;
}

// ============================================================================
// tf32 GEMM — R11 proven: CTA 128x128, 256 thr / 8 warps, warp 32x64,
// K-chunk 32, cp.async 3-stage (96KB), 2 CTAs/SM.
// ============================================================================
enum { EPI_BIAS=0, EPI_BIAS_RES=1, EPI_BIAS_GELU=2 };

template<int EPI, int RND>
__global__ __launch_bounds__(256, 2) void tgemm_kernel(
    const float* __restrict__ A, const float* __restrict__ W,
    const float* __restrict__ bias, const float* __restrict__ res,
    float* __restrict__ C, int M, int N, int K)
{
    extern __shared__ uint32_t sm[];
    const uint32_t smb = (uint32_t)__cvta_generic_to_shared(sm);

    const int tid  = threadIdx.x;
    const int lane = tid & 31;
    const int warp = tid >> 5;
    const int g    = lane >> 2;
    const int tig  = lane & 3;
    const int wm   = (warp & 3) * 32;
    const int wn   = (warp >> 2) * 64;
    const int bm   = blockIdx.y * 128;
    const int bn   = blockIdx.x * 128;

    float acc[2][8][4];
    #pragma unroll
    for (int i=0;i<2;i++)
        #pragma unroll
        for (int j=0;j<8;j++)
            #pragma unroll
            for (int c=0;c<4;c++) acc[i][j][c]=0.f;

    const int r = tid >> 3;
    const int q = tid & 7;
    const int nchunks = K >> 5;

    int istage = 0;
    auto issue = [&](int i){
        const uint32_t aB = smb + (uint32_t)istage*32768u;
        const uint32_t bB = aB + 16384u;
        istage = (istage == 2) ? 0 : istage + 1;
        const int kofs = i << 5;
        #pragma unroll
        for (int it = 0; it < 4; it++){
            const int rr = r + it*32;
            const uint32_t off = ((uint32_t)rr*32u + (uint32_t)((q ^ (rr & 7)) << 2)) * 4u;
            cpa16(aB + off, &A[(size_t)(bm + rr)*K + kofs + q*4]);
            cpa16(bB + off, &W[(size_t)(bn + rr)*K + kofs + q*4]);
        }
        cpa_commit();
    };

    issue(0);
    if (nchunks > 1) issue(1);

    int cstage = 0;
    for (int i = 0; i < nchunks; i++){
        if (i + 2 < nchunks){ issue(i + 2); cpa_wait<2>(); }
        else if (i + 1 < nchunks) cpa_wait<1>();
        else cpa_wait<0>();
        __syncthreads();

        const uint32_t* As = sm + (size_t)cstage*8192;
        const uint32_t* Bs = As + 4096;
        cstage = (cstage == 2) ? 0 : cstage + 1;

        #pragma unroll
        for (int ks = 0; ks < 4; ks++){
            uint32_t af[2][4];
            #pragma unroll
            for (int ii = 0; ii < 2; ii++){
                const int m  = wm + ii*16 + g;
                const int g0 = ((2*ks)   ^ (m & 7)) << 2;
                const int g1 = ((2*ks+1) ^ (m & 7)) << 2;
                af[ii][0] = As[m*32     + g0 + tig];
                af[ii][1] = As[(m+8)*32 + g0 + tig];
                af[ii][2] = As[m*32     + g1 + tig];
                af[ii][3] = As[(m+8)*32 + g1 + tig];
            }
            uint32_t bf[8][2];
            #pragma unroll
            for (int j = 0; j < 8; j++){
                const int n  = wn + j*8 + g;
                const int g0 = ((2*ks)   ^ (n & 7)) << 2;
                const int g1 = ((2*ks+1) ^ (n & 7)) << 2;
                bf[j][0] = Bs[n*32 + g0 + tig];
                bf[j][1] = Bs[n*32 + g1 + tig];
            }
            #pragma unroll
            for (int ii = 0; ii < 2; ii++)
                #pragma unroll
                for (int j = 0; j < 8; j++)
                    mma_tf32(acc[ii][j], af[ii], bf[j]);
        }
        __syncthreads();
    }

    #pragma unroll
    for (int i = 0; i < 2; i++){
        const int row = bm + wm + i*16 + g;
        #pragma unroll
        for (int j = 0; j < 8; j++){
            const int col = bn + wn + j*8 + tig*2;
            const float b0 = bias[col], b1 = bias[col+1];
            float v0 = acc[i][j][0] + b0;
            float v1 = acc[i][j][1] + b1;
            float v2 = acc[i][j][2] + b0;
            float v3 = acc[i][j][3] + b1;
            if (EPI == EPI_BIAS_GELU){
                v0=geluf(v0); v1=geluf(v1); v2=geluf(v2); v3=geluf(v3);
            } else if (EPI == EPI_BIAS_RES){
                const float2 r0 = *reinterpret_cast<const float2*>(&res[(size_t)row*N + col]);
                const float2 r1 = *reinterpret_cast<const float2*>(&res[(size_t)(row+8)*N + col]);
                v0+=r0.x; v1+=r0.y; v2+=r1.x; v3+=r1.y;
            }
            if (RND){
                v0=rna_f(v0); v1=rna_f(v1); v2=rna_f(v2); v3=rna_f(v3);
            }
            *reinterpret_cast<float2*>(&C[(size_t)row*N + col])     = make_float2(v0,v1);
            *reinterpret_cast<float2*>(&C[(size_t)(row+8)*N + col]) = make_float2(v2,v3);
        }
    }
}
#define TG_SMEM (3*8192*4)

// ============================================================================
// tf32 flash attention — R14 proven config: Q-tile 128 (256 thr, 8 warps x 16
// q-rows), KV tile 64, 2-stage KV pipeline, 128KB smem, 1 CTA/SM.
// LPT: qt = 7 - blockIdx.x. Grid (8, B*H).
// smem words: Q @0 (8192), P @8192 (8192), KV stages @16384 (2x8192).
// ============================================================================
#define AQ_OFF 0
#define AP_OFF 8192
#define AKV_OFF(s) (16384 + (s)*8192)
#define ATTN_SMEM (32768*4)

__global__ __launch_bounds__(256) void attn_mma_kernel()
{
    extern __shared__ uint32_t smA[];
    const uint32_t smb = (uint32_t)__cvta_generic_to_shared(smA);
    const int tid  = threadIdx.x;
    const int lane = tid & 31;
    const int warp = tid >> 5;
    const int g    = lane >> 2;
    const int tig  = lane & 3;
    const int wm   = warp * 16;
    const int qt   = (Tn/128 - 1) - blockIdx.x;
    const int bh   = blockIdx.y;
    const int b    = bh >> 4, h = bh & 15;
    const int nkt  = 2*qt + 2;

    {
        const int lr  = tid >> 1;
        const int lg0 = (tid & 1) * 8;
        const float* src = &g_qkv[((size_t)(b*Tn + qt*128 + lr))*QKVN + h*64];
        #pragma unroll
        for (int i = 0; i < 8; i++){
            const int gi = lg0 + i;
            const int gs = ((gi ^ (lr & 7)) & 7) | (gi & 8);
            cpa16(smb + (uint32_t)(AQ_OFF + lr*64 + gs*4)*4u, src + gi*4);
        }
        cpa_commit();
    }
    auto issueKV = [&](int kt){
        const int s   = kt & 1;
        const int kr  = tid >> 2;
        const int kg0 = (tid & 3) * 4;
        const float* srcK = &g_qkv[((size_t)(b*Tn + kt*64 + kr))*QKVN + 1024 + h*64];
        #pragma unroll
        for (int i = 0; i < 4; i++){
            const int gi = kg0 + i;
            const int gs = ((gi ^ (kr & 7)) & 7) | (gi & 8);
            const uint32_t woff = (uint32_t)(kr*64 + gs*4);
            cpa16(smb + (uint32_t)(AKV_OFF(s) + woff)*4u, srcK + gi*4);
            cpa16(smb + (uint32_t)(AKV_OFF(s) + 4096 + woff)*4u, srcK + 1024 + gi*4);
        }
        cpa_commit();
    };
    issueKV(0);

    float M0=-1e30f, M1=-1e30f, L0=0.f, L1=0.f;
    float o[8][4];
    #pragma unroll
    for (int j=0;j<8;j++)
        #pragma unroll
        for (int c=0;c<4;c++) o[j][c]=0.f;

    const uint32_t* Qs = smA + AQ_OFF;
    uint32_t* Ps = smA + AP_OFF;

    for (int kt = 0; kt < nkt; kt++){
        if (kt + 1 < nkt) issueKV(kt + 1);
        if (kt + 1 < nkt) cpa_wait<1>(); else cpa_wait<0>();
        __syncthreads();
        const uint32_t* Ks = smA + AKV_OFF(kt & 1);
        const uint32_t* Vs = Ks + 4096;

        float s[8][4];
        #pragma unroll
        for (int j=0;j<8;j++)
            #pragma unroll
            for (int c=0;c<4;c++) s[j][c]=0.f;

        #pragma unroll
        for (int ks = 0; ks < 8; ks++){
            uint32_t a[4];
            const int m = wm + g;
            a[0] = Qs[fwz(m,   2*ks,   tig)];
            a[1] = Qs[fwz(m+8, 2*ks,   tig)];
            a[2] = Qs[fwz(m,   2*ks+1, tig)];
            a[3] = Qs[fwz(m+8, 2*ks+1, tig)];
            #pragma unroll
            for (int j = 0; j < 8; j++){
                uint32_t bfr[2];
                const int n = 8*j + g;
                bfr[0] = Ks[fwz(n, 2*ks,   tig)];
                bfr[1] = Ks[fwz(n, 2*ks+1, tig)];
                mma_tf32(s[j], a, bfr);
            }
        }

        const bool maybe_mask = (kt >= 2*qt);
        const int gr0 = qt*128 + wm + g;
        const int gr1 = gr0 + 8;
        #pragma unroll
        for (int j = 0; j < 8; j++){
            float v0 = s[j][0]*0.125f, v1 = s[j][1]*0.125f;
            float v2 = s[j][2]*0.125f, v3 = s[j][3]*0.125f;
            if (maybe_mask){
                const int c0 = kt*64 + 8*j + 2*tig, c1 = c0 + 1;
                if (c0 > gr0) v0 = -1e30f;
                if (c1 > gr0) v1 = -1e30f;
                if (c0 > gr1) v2 = -1e30f;
                if (c1 > gr1) v3 = -1e30f;
            }
            s[j][0]=v0; s[j][1]=v1; s[j][2]=v2; s[j][3]=v3;
        }

        float tm0 = -1e30f, tm1 = -1e30f;
        #pragma unroll
        for (int j = 0; j < 8; j++){
            tm0 = fmaxf(tm0, fmaxf(s[j][0], s[j][1]));
            tm1 = fmaxf(tm1, fmaxf(s[j][2], s[j][3]));
        }
        tm0 = fmaxf(tm0, __shfl_xor_sync(0xffffffffu, tm0, 1));
        tm0 = fmaxf(tm0, __shfl_xor_sync(0xffffffffu, tm0, 2));
        tm1 = fmaxf(tm1, __shfl_xor_sync(0xffffffffu, tm1, 1));
        tm1 = fmaxf(tm1, __shfl_xor_sync(0xffffffffu, tm1, 2));
        const float Mn0 = fmaxf(M0, tm0), Mn1 = fmaxf(M1, tm1);
        const float f0 = __expf(M0 - Mn0), f1 = __expf(M1 - Mn1);
        float ps0 = 0.f, ps1 = 0.f;
        #pragma unroll
        for (int j = 0; j < 8; j++){
            const float p0 = __expf(s[j][0] - Mn0);
            const float p1 = __expf(s[j][1] - Mn0);
            const float p2 = __expf(s[j][2] - Mn1);
            const float p3 = __expf(s[j][3] - Mn1);
            ps0 += p0 + p1; ps1 += p2 + p3;
            const int c = 8*j + 2*tig;
            const int gi = c >> 2, off = c & 3;
            uint32_t* p01 = &Ps[fwz(wm+g,   gi, off)];
            uint32_t* p23 = &Ps[fwz(wm+g+8, gi, off)];
            p01[0] = rna_u(__float_as_uint(p0)); p01[1] = rna_u(__float_as_uint(p1));
            p23[0] = rna_u(__float_as_uint(p2)); p23[1] = rna_u(__float_as_uint(p3));
            o[j][0] *= f0; o[j][1] *= f0; o[j][2] *= f1; o[j][3] *= f1;
        }
        ps0 += __shfl_xor_sync(0xffffffffu, ps0, 1);
        ps0 += __shfl_xor_sync(0xffffffffu, ps0, 2);
        ps1 += __shfl_xor_sync(0xffffffffu, ps1, 1);
        ps1 += __shfl_xor_sync(0xffffffffu, ps1, 2);
        L0 = L0*f0 + ps0; L1 = L1*f1 + ps1;
        M0 = Mn0; M1 = Mn1;
        __syncwarp();

        #pragma unroll
        for (int kk = 0; kk < 8; kk++){
            uint32_t a[4];
            const int m = wm + g;
            a[0] = Ps[fwz(m,   2*kk,   tig)];
            a[1] = Ps[fwz(m+8, 2*kk,   tig)];
            a[2] = Ps[fwz(m,   2*kk+1, tig)];
            a[3] = Ps[fwz(m+8, 2*kk+1, tig)];
            #pragma unroll
            for (int j = 0; j < 8; j++){
                uint32_t bfr[2];
                const int n = 8*j + g;
                const int gi = n >> 2, off = n & 3;
                bfr[0] = Vs[fwz(8*kk + tig,     gi, off)];
                bfr[1] = Vs[fwz(8*kk + 4 + tig, gi, off)];
                mma_tf32(o[j], a, bfr);
            }
        }
        __syncthreads();
    }

    const float i0 = 1.f / L0, i1 = 1.f / L1;
    const int r0 = b*Tn + qt*128 + wm + g;
    #pragma unroll
    for (int j = 0; j < 8; j++){
        const int col = h*64 + 8*j + 2*tig;
        *reinterpret_cast<float2*>(&g_seq[(size_t)r0*Dm + col]) =
            make_float2(o[j][0]*i0, o[j][1]*i0);
        *reinterpret_cast<float2*>(&g_seq[(size_t)(r0+8)*Dm + col]) =
            make_float2(o[j][2]*i1, o[j][3]*i1);
    }
}

// ---------------- LayerNorm (tf32-rounded out) ----------------
__global__ __launch_bounds__(256) void ln_kernel(const float* __restrict__ x,
    const float* __restrict__ g, const float* __restrict__ b, float* __restrict__ out)
{
    const int row = blockIdx.x;
    const int tid = threadIdx.x;
    const float4 v = reinterpret_cast<const float4*>(x + (size_t)row*Dm)[tid];
    float s  = v.x+v.y+v.z+v.w;
    float s2 = v.x*v.x+v.y*v.y+v.z*v.z+v.w*v.w;
    #pragma unroll
    for (int off=16; off>0; off>>=1){
        s  += __shfl_xor_sync(0xffffffffu, s,  off);
        s2 += __shfl_xor_sync(0xffffffffu, s2, off);
    }
    __shared__ float ss[8], ss2[8];
    if ((tid & 31)==0){ ss[tid>>5]=s; ss2[tid>>5]=s2; }
    __syncthreads();
    float ts=0.f, ts2=0.f;
    #pragma unroll
    for (int i=0;i<8;i++){ ts+=ss[i]; ts2+=ss2[i]; }
    const float mu  = ts*(1.f/1024.f);
    const float inv = rsqrtf(ts2*(1.f/1024.f) - mu*mu + 1e-5f);
    const float4 gv = reinterpret_cast<const float4*>(g)[tid];
    const float4 bv = reinterpret_cast<const float4*>(b)[tid];
    float4 o;
    o.x=rna_f((v.x-mu)*inv*gv.x+bv.x); o.y=rna_f((v.y-mu)*inv*gv.y+bv.y);
    o.z=rna_f((v.z-mu)*inv*gv.z+bv.z); o.w=rna_f((v.w-mu)*inv*gv.w+bv.w);
    reinterpret_cast<float4*>(out + (size_t)row*Dm)[tid] = o;
}

// ---------------- concat small weights (tf32-rounded, zero-padded to NSP) ----------------
__global__ __launch_bounds__(256) void wcat_kernel(
    const float* __restrict__ w1w, const float* __restrict__ w2w,
    const float* __restrict__ w1r, const float* __restrict__ w2r,
    const float* __restrict__ memg_w, const float* __restrict__ memg_b)
{
    const int r = blockIdx.x;   // 0..NSP-1
    float4* dst = reinterpret_cast<float4*>(g_wcat + (size_t)r*Dm);
    if (r < NSMALL){
        const float* src;
        if      (r < 64)  src = w1w + (size_t)r*Dm;
        else if (r < 128) src = w2w + (size_t)(r-64)*Dm;
        else if (r < 192) src = w1r + (size_t)(r-128)*Dm;
        else if (r < 256) src = w2r + (size_t)(r-192)*Dm;
        else              src = memg_w + (size_t)(r-256)*Dm;
        float4 v = reinterpret_cast<const float4*>(src)[threadIdx.x];
        v.x=rna_f(v.x); v.y=rna_f(v.y); v.z=rna_f(v.z); v.w=rna_f(v.w);
        dst[threadIdx.x] = v;
    } else {
        dst[threadIdx.x] = make_float4(0.f,0.f,0.f,0.f);
    }
    if (r == 0){
        for (int c = threadIdx.x; c < NSP; c += 256)
            g_bcat[c] = (c >= 256 && c < NSMALL) ? memg_b[c-256] : 0.f;
    }
}

// ---------------- Plucker lines + J permutation (stride NSP) ----------------
__global__ __launch_bounds__(256) void lines_kernel()
{
    const int idx = blockIdx.x*256 + threadIdx.x;
    const int row = idx >> 4;
    const int h   = idx & 15;
    const int b   = row >> 10;
    const int t   = row & 1023;
    const float* s = g_small + (size_t)row*NSP;

    float p1[4], p2[4], L[6];
    if (t == 0){ p1[0]=p1[1]=p1[2]=p1[3]=0.f; }
    else {
        const float* sp = s - NSP;
        #pragma unroll
        for (int p=0;p<4;p++) p1[p] = sp[h*4+p];
    }
    #pragma unroll
    for (int p=0;p<4;p++) p2[p] = s[64 + h*4 + p];

    L[0]=p1[0]*p2[1]-p1[1]*p2[0];
    L[1]=p1[0]*p2[2]-p1[2]*p2[0];
    L[2]=p1[0]*p2[3]-p1[3]*p2[0];
    L[3]=p1[1]*p2[2]-p1[2]*p2[1];
    L[4]=p1[1]*p2[3]-p1[3]*p2[1];
    L[5]=p1[2]*p2[3]-p1[3]*p2[2];
    float nn = sqrtf(L[0]*L[0]+L[1]*L[1]+L[2]*L[2]+L[3]*L[3]+L[4]*L[4]+L[5]*L[5]);
    float inv = 1.f / fmaxf(nn, 1e-12f);
    float* jw = &g_jw[(((size_t)(b*Hn+h))*Tn + t)*8];
    jw[0]= L[5]*inv; jw[1]=-L[4]*inv; jw[2]= L[3]*inv;
    jw[3]= L[2]*inv; jw[4]=-L[1]*inv; jw[5]= L[0]*inv;
    jw[6]=0.f; jw[7]=0.f;

    #pragma unroll
    for (int p=0;p<4;p++){ p1[p]=s[128+h*4+p]; p2[p]=s[192+h*4+p]; }
    L[0]=p1[0]*p2[1]-p1[1]*p2[0];
    L[1]=p1[0]*p2[2]-p1[2]*p2[0];
    L[2]=p1[0]*p2[3]-p1[3]*p2[0];
    L[3]=p1[1]*p2[2]-p1[2]*p2[1];
    L[4]=p1[1]*p2[3]-p1[3]*p2[1];
    L[5]=p1[2]*p2[3]-p1[3]*p2[2];
    nn = sqrtf(L[0]*L[0]+L[1]*L[1]+L[2]*L[2]+L[3]*L[3]+L[4]*L[4]+L[5]*L[5]);
    inv = 1.f / fmaxf(nn, 1e-12f);
    float* rl = &g_rl[(((size_t)(b*Hn+h))*Tn + t)*6];
    #pragma unroll
    for (int p=0;p<6;p++) rl[p] = L[p]*inv;
}

// ---------------- decay^delta table ----------------
__global__ void pow_kernel(const float* __restrict__ decay_logits)
{
    const int h = blockIdx.x;
    const float d  = 1.f/(1.f+expf(-decay_logits[h]));
    const float l2 = log2f(d);
    for (int t = threadIdx.x; t < Tn; t += blockDim.x)
        g_powd[h*Tn + t] = exp2f((float)t * l2);
}

// ---------------- mem_score: grid (bh, 4 q-chunks of 256) ----------------
__global__ __launch_bounds__(256) void mscore_kernel()
{
    const int bh = blockIdx.x;
    const int qc = blockIdx.y;
    const int h  = bh & 15;
    const int jmax = (qc + 1) * 256;
    __shared__ float jw_s[Tn*8];
    __shared__ float pw_s[Tn];
    const int tid = threadIdx.x;
    for (int i = tid; i < jmax*2; i += 256)
        reinterpret_cast<float4*>(jw_s)[i] =
            reinterpret_cast<const float4*>(g_jw + (size_t)bh*Tn*8)[i];
    for (int i = tid; i < Tn; i += 256) pw_s[i] = g_powd[h*Tn + i];
    __syncthreads();

    const int q = qc*256 + tid;
    float r0,r1,r2,r3,r4,r5;
    const float* rp = &g_rl[((size_t)bh*Tn + q)*6];
    r0=rp[0]; r1=rp[1]; r2=rp[2]; r3=rp[3]; r4=rp[4]; r5=rp[5];
    float acc = 0.f;
    for (int j = 0; j < q; j++){
        const float2 w0 = *reinterpret_cast<const float2*>(&jw_s[j*8+0]);
        const float2 w1 = *reinterpret_cast<const float2*>(&jw_s[j*8+2]);
        const float2 w2 = *reinterpret_cast<const float2*>(&jw_s[j*8+4]);
        float dot = r0*w0.x;
        dot = fmaf(r1, w0.y, dot);
        dot = fmaf(r2, w1.x, dot);
        dot = fmaf(r3, w1.y, dot);
        dot = fmaf(r4, w2.x, dot);
        dot = fmaf(r5, w2.y, dot);
        acc = fmaf(fabsf(dot), pw_s[q-j], acc);
    }
    g_mscore[(size_t)bh*Tn + q] = acc;
}

// ---------------- gated+fuse merged (stride NSP) ----------------
__global__ __launch_bounds__(256) void gatedfuse_kernel(const float* __restrict__ mem_scale)
{
    const int row = blockIdx.x;
    const int b = row >> 10, t = row & 1023;
    const int tid = threadIdx.x;
    __shared__ float gv_s;
    if (tid < 16){
        const float ms = g_mscore[(size_t)(b*Hn+tid)*Tn + t];
        const float gt = sigf(g_small[(size_t)row*NSP + 256 + tid]);
        float v = sigf(ms * mem_scale[tid]) * gt;
        v += __shfl_xor_sync(0xffffu, v, 1, 16);
        v += __shfl_xor_sync(0xffffu, v, 2, 16);
        v += __shfl_xor_sync(0xffffu, v, 4, 16);
        v += __shfl_xor_sync(0xffffu, v, 8, 16);
        if (tid == 0) gv_s = v * (1.f/16.f);
    }
    __syncthreads();
    const float gv = gv_s;
    float4* sp = reinterpret_cast<float4*>(&g_seq[(size_t)row*Dm]);
    const float4* mp = reinterpret_cast<const float4*>(&g_qkv[(size_t)row*QKVN + 3072]);
    float4 s = sp[tid];
    const float4 m = mp[tid];
    s.x = rna_f(fmaf(gv, m.x, s.x)); s.y = rna_f(fmaf(gv, m.y, s.y));
    s.z = rna_f(fmaf(gv, m.z, s.z)); s.w = rna_f(fmaf(gv, m.w, s.w));
    sp[tid] = s;
}

// ---------------- launcher ----------------
extern "C" void kernel_launch(void* const* d_in, const int* in_sizes, int n_in,
                              void* d_out, int out_size)
{
    const float* x            = (const float*)d_in[0];
    const float* ln1_g        = (const float*)d_in[1];
    const float* ln1_b        = (const float*)d_in[2];
    const float* qkv_w        = (const float*)d_in[3];
    const float* qkv_b        = (const float*)d_in[4];
    const float* w1w          = (const float*)d_in[5];
    const float* w2w          = (const float*)d_in[6];
    const float* w1r          = (const float*)d_in[7];
    const float* w2r          = (const float*)d_in[8];
    const float* memv_w       = (const float*)d_in[9];
    const float* memv_b       = (const float*)d_in[10];
    const float* memg_w       = (const float*)d_in[11];
    const float* memg_b       = (const float*)d_in[12];
    const float* mem_scale    = (const float*)d_in[13];
    const float* out_w        = (const float*)d_in[14];
    const float* out_b        = (const float*)d_in[15];
    const float* decay_logits = (const float*)d_in[16];
    const float* ln2_g        = (const float*)d_in[17];
    const float* ln2_b        = (const float*)d_in[18];
    const float* fc1_w        = (const float*)d_in[19];
    const float* fc1_b        = (const float*)d_in[20];
    const float* fc2_w        = (const float*)d_in[21];
    const float* fc2_b        = (const float*)d_in[22];
    float* out = (float*)d_out;

    float *ph, *pqkv, *psmall, *pseq, *px2, *ph2, *pff1;
    cudaGetSymbolAddress((void**)&ph,     g_h);
    cudaGetSymbolAddress((void**)&pqkv,   g_qkv);
    cudaGetSymbolAddress((void**)&psmall, g_small);
    cudaGetSymbolAddress((void**)&pseq,   g_seq);
    cudaGetSymbolAddress((void**)&px2,    g_x2);
    cudaGetSymbolAddress((void**)&ph2,    g_h2);
    cudaGetSymbolAddress((void**)&pff1,   g_ff1);
    float *pwcat, *pbcat, *pwqkv, *pbqkvm, *pwout, *pwfc1, *pwfc2;
    cudaGetSymbolAddress((void**)&pwcat,  g_wcat);
    cudaGetSymbolAddress((void**)&pbcat,  g_bcat);
    cudaGetSymbolAddress((void**)&pwqkv,  g_wqkv);
    cudaGetSymbolAddress((void**)&pbqkvm, g_bqkvm);
    cudaGetSymbolAddress((void**)&pwout,  g_wout);
    cudaGetSymbolAddress((void**)&pwfc1,  g_wfc1);
    cudaGetSymbolAddress((void**)&pwfc2,  g_wfc2);

    cudaFuncSetAttribute(tgemm_kernel<EPI_BIAS,1>,      cudaFuncAttributeMaxDynamicSharedMemorySize, TG_SMEM);
    cudaFuncSetAttribute(tgemm_kernel<EPI_BIAS,0>,      cudaFuncAttributeMaxDynamicSharedMemorySize, TG_SMEM);
    cudaFuncSetAttribute(tgemm_kernel<EPI_BIAS_RES,0>,  cudaFuncAttributeMaxDynamicSharedMemorySize, TG_SMEM);
    cudaFuncSetAttribute(tgemm_kernel<EPI_BIAS_GELU,1>, cudaFuncAttributeMaxDynamicSharedMemorySize, TG_SMEM);
    cudaFuncSetAttribute(attn_mma_kernel,               cudaFuncAttributeMaxDynamicSharedMemorySize, ATTN_SMEM);

    // (1) roundw (2) ln1 (3) qkv (4) attn <- profiled
    roundw_all_kernel<<<(N4_TOT+255)/256, 256>>>((const float4*)qkv_w, (const float4*)memv_w,
                                                 (const float4*)out_w, (const float4*)fc1_w,
                                                 (const float4*)fc2_w, (const float4*)qkv_b,
                                                 (const float4*)memv_b);
    ln_kernel<<<Mrows, 256>>>(x, ln1_g, ln1_b, ph);

    // merged qkv+memval: [4096, 4096]
    tgemm_kernel<EPI_BIAS,1><<<dim3(32,32), 256, TG_SMEM>>>(ph, pwqkv, pbqkvm, nullptr, pqkv, Mrows, QKVN, Dm);

    attn_mma_kernel<<<dim3(Tn/128, Bsz*Hn), 256, ATTN_SMEM>>>();

    wcat_kernel<<<NSP, 256>>>(w1w, w2w, w1r, w2r, memg_w, memg_b);
    pow_kernel<<<Hn, 256>>>(decay_logits);
    // small projections on tensor cores: [4096, 384] tf32
    tgemm_kernel<EPI_BIAS,0><<<dim3(3,32), 256, TG_SMEM>>>(ph, pwcat, pbcat, nullptr, psmall, Mrows, NSP, Dm);
    lines_kernel<<<Mrows*Hn/256, 256>>>();
    mscore_kernel<<<dim3(Bsz*Hn, Tn/256), 256>>>();
    gatedfuse_kernel<<<Mrows, 256>>>(mem_scale);

    // out proj + residual x -> x2
    tgemm_kernel<EPI_BIAS_RES,0><<<dim3(8,32), 256, TG_SMEM>>>(pseq, pwout, out_b, x, px2, Mrows, Dm, Dm);
    // LN2
    ln_kernel<<<Mrows, 256>>>(px2, ln2_g, ln2_b, ph2);
    // fc1 + gelu (tf32): [4096,4096]
    tgemm_kernel<EPI_BIAS_GELU,1><<<dim3(32,32), 256, TG_SMEM>>>(ph2, pwfc1, fc1_b, nullptr, pff1, Mrows, DFFn, Dm);
    // fc2 + bias + residual (tf32) -> out
    tgemm_kernel<EPI_BIAS_RES,0><<<dim3(8,32), 256, TG_SMEM>>>(pff1, pwfc2, fc2_b, px2, out, Mrows, Dm, DFFn);
}